// round 1
// baseline (speedup 1.0000x reference)
#include <cuda_runtime.h>
#include <math.h>
#include <stdint.h>

// ---------------- problem constants ----------------
#define Bc 4
#define Nc 1500
#define Kc 30
#define Hc 128
#define Lc 4
#define BNc (Bc*Nc)          // 6000
#define ECNT (BNc*Kc)        // 180000

// ---------------- device scratch (no allocations allowed) ----------------
__device__ int   g_Eidx[ECNT];
__device__ float g_Dnb[ECNT];
__device__ float g_feat[(size_t)ECNT*32];
__device__ float g_hE[(size_t)ECNT*128];
__device__ float g_hEV[(size_t)ECNT*256];
__device__ float g_Kh[(size_t)ECNT*128];
__device__ float g_Vh[(size_t)ECNT*128];
__device__ float g_hVa[(size_t)BNc*128];
__device__ float g_hVb[(size_t)BNc*128];
__device__ float g_hVm[(size_t)BNc*128];
__device__ float g_Q[(size_t)BNc*128];
__device__ float g_att[(size_t)BNc*128];
__device__ float g_upd[(size_t)BNc*128];
__device__ float g_ff[(size_t)BNc*512];

// ---------------- top-K nearest neighbors ----------------
// One block per (b,i) row. Computes D row into shared, row max, D_adj,
// then 30 sequential argmin rounds (tie -> lower index, matching lax.top_k).
__global__ void topk_kernel(const float* __restrict__ X, const float* __restrict__ mask,
                            int* __restrict__ Eidx, float* __restrict__ Dnb)
{
    __shared__ float sD[Nc];
    __shared__ float rv[256];
    __shared__ int   ri[256];
    __shared__ float s_rowmax;
    int row = blockIdx.x;            // b*N + i
    int b = row / Nc;
    int i = row - b * Nc;
    int tid = threadIdx.x;
    const float* Xb = X + (size_t)b * Nc * 3;
    const float* mb = mask + (size_t)b * Nc;
    float xi0 = Xb[i*3+0], xi1 = Xb[i*3+1], xi2 = Xb[i*3+2];
    float mi = mb[i];
    float lmax = 0.f;
    for (int j = tid; j < Nc; j += 256) {
        float dx = xi0 - Xb[j*3+0];
        float dy = xi1 - Xb[j*3+1];
        float dz = xi2 - Xb[j*3+2];
        float d = sqrtf(dx*dx + dy*dy + dz*dz + 1e-6f);
        float D = mi * mb[j] * d;
        sD[j] = D;
        lmax = fmaxf(lmax, D);
    }
    rv[tid] = lmax;
    __syncthreads();
    for (int s = 128; s > 0; s >>= 1) {
        if (tid < s) rv[tid] = fmaxf(rv[tid], rv[tid+s]);
        __syncthreads();
    }
    if (tid == 0) s_rowmax = rv[0];
    __syncthreads();
    float rowmax = s_rowmax;
    for (int j = tid; j < Nc; j += 256) {
        float m2 = mi * mb[j];
        sD[j] = sD[j] + (1.f - m2) * rowmax;
    }
    __syncthreads();
    for (int sel = 0; sel < Kc; sel++) {
        float bv = 3.3e38f; int bi = 0x7fffffff;
        for (int j = tid; j < Nc; j += 256) {
            float v = sD[j];
            if (v < bv) { bv = v; bi = j; }
        }
        rv[tid] = bv; ri[tid] = bi;
        __syncthreads();
        for (int s = 128; s > 0; s >>= 1) {
            if (tid < s) {
                float ov = rv[tid+s]; int oi = ri[tid+s];
                if (ov < rv[tid] || (ov == rv[tid] && oi < ri[tid])) { rv[tid]=ov; ri[tid]=oi; }
            }
            __syncthreads();
        }
        if (tid == 0) {
            Eidx[(size_t)row*Kc + sel] = ri[0];
            Dnb [(size_t)row*Kc + sel] = rv[0];
            sD[ri[0]] = 3.4e38f;
        }
        __syncthreads();
    }
}

// ---------------- edge features: [cos(8), sin(8), rbf(16)] ----------------
__global__ void edge_feat_kernel(const int* __restrict__ Eidx, const float* __restrict__ Dnb,
                                 float* __restrict__ feat)
{
    int t = blockIdx.x * 256 + threadIdx.x;
    if (t >= ECNT * 32) return;
    int e = t >> 5;
    int c = t & 31;
    float val;
    if (c < 16) {
        int m = c & 7;
        float freq = expf((float)(2*m) * (-9.210340371976184f / 16.f)); // -ln(10000)/NUM_POS
        int node = e / Kc;
        int i = node % Nc;
        float d_rel = (float)(Eidx[e] - i);
        float ang = d_rel * freq;
        val = (c < 8) ? cosf(ang) : sinf(ang);
    } else {
        int r = c - 16;
        float mu = 20.f * (float)r / 15.f;   // linspace(0,20,16)
        float tt = (Dnb[e] - mu) * (1.f / 1.25f);  // sigma = 20/16
        val = expf(-tt * tt);
    }
    feat[(size_t)t] = val;
}

// ---------------- generic SGEMM: C[M,N] = A[M,K]@B[K,N] (+bias)(relu) ----------------
// BM=BN=128, BK=8, TM=TN=8, 256 threads. K%8==0, N%128==0 required. M guarded.
template<int BIAS, int RELU>
__global__ void __launch_bounds__(256)
sgemm_kernel(const float* __restrict__ A, const float* __restrict__ Bm,
             const float* __restrict__ bias, float* __restrict__ C,
             int M, int Nn, int Kk)
{
    constexpr int BM=128, BN=128, BK=8, TM=8, TN=8;
    __shared__ float As[BK][BM];
    __shared__ float Bs[BK][BN];
    int tid = threadIdx.x;
    int cRow = blockIdx.y, cCol = blockIdx.x;
    const float* Ab = A + (size_t)cRow * BM * Kk;
    const float* Bb = Bm + (size_t)cCol * BN;
    int innerRowA = tid >> 1;
    int innerColA = (tid & 1) * 4;
    int innerRowB = tid >> 5;
    int innerColB = (tid & 31) * 4;
    int threadRow = (tid >> 4) * TM;
    int threadCol = (tid & 15) * TN;
    bool aValid = (cRow * BM + innerRowA) < M;

    float acc[TM][TN];
    #pragma unroll
    for (int i2 = 0; i2 < TM; i2++)
        #pragma unroll
        for (int j2 = 0; j2 < TN; j2++) acc[i2][j2] = 0.f;

    for (int k0 = 0; k0 < Kk; k0 += BK) {
        float4 av = aValid ? *(const float4*)(Ab + (size_t)innerRowA * Kk + k0 + innerColA)
                           : make_float4(0.f, 0.f, 0.f, 0.f);
        As[innerColA+0][innerRowA] = av.x;
        As[innerColA+1][innerRowA] = av.y;
        As[innerColA+2][innerRowA] = av.z;
        As[innerColA+3][innerRowA] = av.w;
        float4 bv = *(const float4*)(Bb + (size_t)(k0 + innerRowB) * Nn + innerColB);
        *(float4*)(&Bs[innerRowB][innerColB]) = bv;
        __syncthreads();
        #pragma unroll
        for (int kk = 0; kk < BK; kk++) {
            float4 m0 = *(const float4*)(&As[kk][threadRow]);
            float4 m1 = *(const float4*)(&As[kk][threadRow+4]);
            float4 n0 = *(const float4*)(&Bs[kk][threadCol]);
            float4 n1 = *(const float4*)(&Bs[kk][threadCol+4]);
            float regM[TM] = {m0.x,m0.y,m0.z,m0.w,m1.x,m1.y,m1.z,m1.w};
            float regN[TN] = {n0.x,n0.y,n0.z,n0.w,n1.x,n1.y,n1.z,n1.w};
            #pragma unroll
            for (int i2 = 0; i2 < TM; i2++)
                #pragma unroll
                for (int j2 = 0; j2 < TN; j2++)
                    acc[i2][j2] += regM[i2] * regN[j2];
        }
        __syncthreads();
    }

    float bvals[TN];
    #pragma unroll
    for (int j2 = 0; j2 < TN; j2++)
        bvals[j2] = BIAS ? bias[cCol * BN + threadCol + j2] : 0.f;

    #pragma unroll
    for (int i2 = 0; i2 < TM; i2++) {
        int gr = cRow * BM + threadRow + i2;
        if (gr >= M) break;
        float* Crow = C + (size_t)gr * Nn + cCol * BN + threadCol;
        #pragma unroll
        for (int j2 = 0; j2 < TN; j2 += 4) {
            float4 o;
            o.x = acc[i2][j2+0] + bvals[j2+0];
            o.y = acc[i2][j2+1] + bvals[j2+1];
            o.z = acc[i2][j2+2] + bvals[j2+2];
            o.w = acc[i2][j2+3] + bvals[j2+3];
            if (RELU) { o.x=fmaxf(o.x,0.f); o.y=fmaxf(o.y,0.f); o.z=fmaxf(o.z,0.f); o.w=fmaxf(o.w,0.f); }
            *(float4*)(Crow + j2) = o;
        }
    }
}

// ---------------- gather + concat: h_EV = [h_E, h_V[E_idx]] ----------------
__global__ void gather_kernel(const float* __restrict__ hE, const float* __restrict__ hV,
                              const int* __restrict__ Eidx, float* __restrict__ hEV)
{
    int e = blockIdx.x;
    int c = threadIdx.x;  // 256
    float v;
    if (c < 128) {
        v = hE[(size_t)e * 128 + c];
    } else {
        int node = e / Kc;
        int b = node / Nc;
        int j = Eidx[e];
        v = hV[((size_t)b * Nc + j) * 128 + (c - 128)];
    }
    hEV[(size_t)e * 256 + c] = v;
}

// ---------------- attention: one block per node, one warp per head ----------------
__global__ void attn_kernel(const float* __restrict__ Q, const float* __restrict__ Kh,
                            const float* __restrict__ Vh, const int* __restrict__ Eidx,
                            const float* __restrict__ mask, float* __restrict__ out)
{
    int node = blockIdx.x;
    int tid = threadIdx.x;     // 128
    int h = tid >> 5, lane = tid & 31;
    __shared__ float lg[4][32];
    __shared__ float smk[32];
    int b = node / Nc;
    if (tid < Kc) smk[tid] = mask[(size_t)b * Nc + Eidx[(size_t)node * Kc + tid]];
    __syncthreads();
    float mi = mask[node];
    float q = Q[(size_t)node * 128 + tid];
    for (int k = 0; k < Kc; k++) {
        float p = q * Kh[((size_t)node * Kc + k) * 128 + tid];
        #pragma unroll
        for (int o = 16; o > 0; o >>= 1) p += __shfl_xor_sync(0xffffffffu, p, o);
        if (lane == 0) lg[h][k] = p * 0.17677669529663687f;  // 1/sqrt(32)
    }
    __syncwarp();
    float x = -3.4e38f, mk = 0.f;
    if (lane < Kc) {
        mk = mi * smk[lane];
        x = (mk > 0.f) ? lg[h][lane] : -3.4028235e38f;
    }
    float mx = x;
    #pragma unroll
    for (int o = 16; o > 0; o >>= 1) mx = fmaxf(mx, __shfl_xor_sync(0xffffffffu, mx, o));
    float ex = (lane < Kc) ? expf(x - mx) : 0.f;
    float sm = ex;
    #pragma unroll
    for (int o = 16; o > 0; o >>= 1) sm += __shfl_xor_sync(0xffffffffu, sm, o);
    float a = (lane < Kc) ? (ex / sm) * mk : 0.f;
    if (lane < Kc) lg[h][lane] = a;
    __syncwarp();
    float acc = 0.f;
    for (int k = 0; k < Kc; k++)
        acc += lg[h][k] * Vh[((size_t)node * Kc + k) * 128 + tid];
    out[(size_t)node * 128 + tid] = acc;
}

// ---------------- layer norm over width 128 (+optional residual, mask) ----------------
__global__ void ln_kernel(const float* __restrict__ x, const float* __restrict__ res,
                          const float* __restrict__ gamma, const float* __restrict__ beta,
                          const float* __restrict__ mask, float* __restrict__ out)
{
    int row = blockIdx.x;
    int c = threadIdx.x;  // 128
    float v = x[(size_t)row * 128 + c];
    if (res) v += res[(size_t)row * 128 + c];
    float s = v, s2 = v * v;
    #pragma unroll
    for (int o = 16; o > 0; o >>= 1) {
        s  += __shfl_xor_sync(0xffffffffu, s,  o);
        s2 += __shfl_xor_sync(0xffffffffu, s2, o);
    }
    __shared__ float ws[4], ws2[4];
    int w = c >> 5;
    if ((c & 31) == 0) { ws[w] = s; ws2[w] = s2; }
    __syncthreads();
    s  = ws[0] + ws[1] + ws[2] + ws[3];
    s2 = ws2[0] + ws2[1] + ws2[2] + ws2[3];
    float mu = s * (1.f / 128.f);
    float var = s2 * (1.f / 128.f) - mu * mu;
    float y = gamma[c] * (v - mu) * rsqrtf(var + 1e-6f) + beta[c];
    if (mask) y *= mask[row];
    out[(size_t)row * 128 + c] = y;
}

// ---------------- final projection: out[b,n] = h_V @ W_out + b_out ----------------
__global__ void out_kernel(const float* __restrict__ hV, const float* __restrict__ Wout,
                           const float* __restrict__ bout, float* __restrict__ out)
{
    int node = blockIdx.x * 4 + (threadIdx.x >> 5);
    int lane = threadIdx.x & 31;
    if (node >= BNc) return;
    float acc = 0.f;
    #pragma unroll
    for (int m = 0; m < 4; m++)
        acc += hV[(size_t)node * 128 + lane + m * 32] * Wout[lane + m * 32];
    #pragma unroll
    for (int o = 16; o > 0; o >>= 1) acc += __shfl_xor_sync(0xffffffffu, acc, o);
    if (lane == 0) out[node] = acc + bout[0];
}

// ---------------- host launch ----------------
static void* symaddr(const void* sym) { void* p = nullptr; cudaGetSymbolAddress(&p, sym); return p; }

extern "C" void kernel_launch(void* const* d_in, const int* in_sizes, int n_in,
                              void* d_out, int out_size)
{
    const float* X      = (const float*)d_in[0];
    const float* V      = (const float*)d_in[1];
    const float* mask   = (const float*)d_in[2];
    const float* W_v    = (const float*)d_in[3];
    const float* b_v    = (const float*)d_in[4];
    const float* W_e    = (const float*)d_in[5];
    const float* b_e    = (const float*)d_in[6];
    const float* W_edge = (const float*)d_in[7];
    const float* ln_e_g = (const float*)d_in[8];
    const float* ln_e_b = (const float*)d_in[9];
    const float* Wq     = (const float*)d_in[10];
    const float* Wk     = (const float*)d_in[11];
    const float* Wv_a   = (const float*)d_in[12];
    const float* Wo     = (const float*)d_in[13];
    const float* ln1_g  = (const float*)d_in[14];
    const float* ln1_b  = (const float*)d_in[15];
    const float* ln2_g  = (const float*)d_in[16];
    const float* ln2_b  = (const float*)d_in[17];
    const float* W_ff1  = (const float*)d_in[18];
    const float* b_ff1  = (const float*)d_in[19];
    const float* W_ff2  = (const float*)d_in[20];
    const float* b_ff2  = (const float*)d_in[21];
    const float* W_out  = (const float*)d_in[22];
    const float* b_out  = (const float*)d_in[23];
    float* out = (float*)d_out;

    int*   pEidx = (int*)  symaddr(g_Eidx);
    float* pDnb  = (float*)symaddr(g_Dnb);
    float* pFeat = (float*)symaddr(g_feat);
    float* phE   = (float*)symaddr(g_hE);
    float* phEV  = (float*)symaddr(g_hEV);
    float* pKh   = (float*)symaddr(g_Kh);
    float* pVh   = (float*)symaddr(g_Vh);
    float* phVa  = (float*)symaddr(g_hVa);
    float* phVb  = (float*)symaddr(g_hVb);
    float* phVm  = (float*)symaddr(g_hVm);
    float* pQ    = (float*)symaddr(g_Q);
    float* pAtt  = (float*)symaddr(g_att);
    float* pUpd  = (float*)symaddr(g_upd);
    float* pFF   = (float*)symaddr(g_ff);

    const int gE = (ECNT + 127) / 128;   // 1407 row-blocks for M=180000
    const int gN = (BNc + 127) / 128;    // 47 row-blocks for M=6000

    // 1. top-K neighbors
    topk_kernel<<<BNc, 256>>>(X, mask, pEidx, pDnb);
    // 2. edge features (pos16 + rbf16)
    edge_feat_kernel<<<(ECNT * 32 + 255) / 256, 256>>>(pEidx, pDnb, pFeat);
    // 3. E = feat @ W_edge   (use pKh as temp for E)
    sgemm_kernel<0,0><<<dim3(1, gE), 256>>>(pFeat, W_edge, nullptr, pKh, ECNT, 128, 32);
    // 4. E = LN(E)
    ln_kernel<<<ECNT, 128>>>(pKh, nullptr, ln_e_g, ln_e_b, nullptr, pKh);
    // 5. h_E = E @ W_e + b_e
    sgemm_kernel<1,0><<<dim3(1, gE), 256>>>(pKh, W_e, b_e, phE, ECNT, 128, 128);
    // 6. h_V = V @ W_v + b_v
    sgemm_kernel<1,0><<<dim3(1, gN), 256>>>(V, W_v, b_v, phVa, BNc, 128, 1024);

    float* cur = phVa;
    float* nxt = phVb;
    for (int l = 0; l < Lc; l++) {
        gather_kernel<<<ECNT, 256>>>(phE, cur, pEidx, phEV);
        sgemm_kernel<0,0><<<dim3(1, gE), 256>>>(phEV, Wk   + (size_t)l*256*128, nullptr, pKh, ECNT, 128, 256);
        sgemm_kernel<0,0><<<dim3(1, gE), 256>>>(phEV, Wv_a + (size_t)l*256*128, nullptr, pVh, ECNT, 128, 256);
        sgemm_kernel<0,0><<<dim3(1, gN), 256>>>(cur,  Wq   + (size_t)l*128*128, nullptr, pQ,  BNc, 128, 128);
        attn_kernel<<<BNc, 128>>>(pQ, pKh, pVh, pEidx, mask, pAtt);
        sgemm_kernel<0,0><<<dim3(1, gN), 256>>>(pAtt, Wo + (size_t)l*128*128, nullptr, pUpd, BNc, 128, 128);
        ln_kernel<<<BNc, 128>>>(pUpd, cur, ln1_g + l*128, ln1_b + l*128, nullptr, phVm);
        sgemm_kernel<1,1><<<dim3(4, gN), 256>>>(phVm, W_ff1 + (size_t)l*128*512, b_ff1 + l*512, pFF, BNc, 512, 128);
        sgemm_kernel<1,0><<<dim3(1, gN), 256>>>(pFF,  W_ff2 + (size_t)l*512*128, b_ff2 + l*128, pUpd, BNc, 128, 512);
        ln_kernel<<<BNc, 128>>>(pUpd, phVm, ln2_g + l*128, ln2_b + l*128, mask, nxt);
        float* t = cur; cur = nxt; nxt = t;
    }
    out_kernel<<<(BNc + 3) / 4, 128>>>(cur, W_out, b_out, out);
}

// round 2
// speedup vs baseline: 1.3684x; 1.3684x over previous
#include <cuda_runtime.h>
#include <math.h>
#include <stdint.h>

// ---------------- problem constants ----------------
#define Bc 4
#define Nc 1500
#define Kc 30
#define Hc 128
#define Lc 4
#define BNc (Bc*Nc)          // 6000
#define ECNT (BNc*Kc)        // 180000

// ---------------- device scratch ----------------
__device__ int   g_Eidx[ECNT];
__device__ float g_Dnb[ECNT];
__device__ float g_feat[(size_t)ECNT*32];
__device__ float g_Etmp[(size_t)ECNT*128];
__device__ float g_hE[(size_t)ECNT*128];
__device__ float g_hVa[(size_t)BNc*128];
__device__ float g_hVb[(size_t)BNc*128];
__device__ float g_hVm[(size_t)BNc*128];
__device__ float g_Q[(size_t)BNc*128];
__device__ float g_Kn[(size_t)BNc*128];
__device__ float g_Vn[(size_t)BNc*128];
__device__ float g_qe[(size_t)BNc*512];
__device__ float g_att[(size_t)BNc*128];
__device__ float g_upd[(size_t)BNc*128];
__device__ float g_ff[(size_t)BNc*512];

// ---------------- top-K nearest neighbors ----------------
__global__ void topk_kernel(const float* __restrict__ X, const float* __restrict__ mask,
                            int* __restrict__ Eidx, float* __restrict__ Dnb)
{
    __shared__ float sD[Nc];
    __shared__ float rv[256];
    __shared__ int   ri[256];
    __shared__ float s_rowmax;
    int row = blockIdx.x;            // b*N + i
    int b = row / Nc;
    int i = row - b * Nc;
    int tid = threadIdx.x;
    const float* Xb = X + (size_t)b * Nc * 3;
    const float* mb = mask + (size_t)b * Nc;
    float xi0 = Xb[i*3+0], xi1 = Xb[i*3+1], xi2 = Xb[i*3+2];
    float mi = mb[i];
    float lmax = 0.f;
    for (int j = tid; j < Nc; j += 256) {
        float dx = xi0 - Xb[j*3+0];
        float dy = xi1 - Xb[j*3+1];
        float dz = xi2 - Xb[j*3+2];
        float d = sqrtf(dx*dx + dy*dy + dz*dz + 1e-6f);
        float D = mi * mb[j] * d;
        sD[j] = D;
        lmax = fmaxf(lmax, D);
    }
    rv[tid] = lmax;
    __syncthreads();
    for (int s = 128; s > 0; s >>= 1) {
        if (tid < s) rv[tid] = fmaxf(rv[tid], rv[tid+s]);
        __syncthreads();
    }
    if (tid == 0) s_rowmax = rv[0];
    __syncthreads();
    float rowmax = s_rowmax;
    for (int j = tid; j < Nc; j += 256) {
        float m2 = mi * mb[j];
        sD[j] = sD[j] + (1.f - m2) * rowmax;
    }
    __syncthreads();
    for (int sel = 0; sel < Kc; sel++) {
        float bv = 3.3e38f; int bi = 0x7fffffff;
        for (int j = tid; j < Nc; j += 256) {
            float v = sD[j];
            if (v < bv) { bv = v; bi = j; }
        }
        rv[tid] = bv; ri[tid] = bi;
        __syncthreads();
        for (int s = 128; s > 0; s >>= 1) {
            if (tid < s) {
                float ov = rv[tid+s]; int oi = ri[tid+s];
                if (ov < rv[tid] || (ov == rv[tid] && oi < ri[tid])) { rv[tid]=ov; ri[tid]=oi; }
            }
            __syncthreads();
        }
        if (tid == 0) {
            Eidx[(size_t)row*Kc + sel] = ri[0];
            Dnb [(size_t)row*Kc + sel] = rv[0];
            sD[ri[0]] = 3.4e38f;
        }
        __syncthreads();
    }
}

// ---------------- edge features: [cos(8), sin(8), rbf(16)] ----------------
__global__ void edge_feat_kernel(const int* __restrict__ Eidx, const float* __restrict__ Dnb,
                                 float* __restrict__ feat)
{
    int t = blockIdx.x * 256 + threadIdx.x;
    if (t >= ECNT * 32) return;
    int e = t >> 5;
    int c = t & 31;
    float val;
    if (c < 16) {
        int m = c & 7;
        float freq = expf((float)(2*m) * (-9.210340371976184f / 16.f));
        int node = e / Kc;
        int i = node % Nc;
        float d_rel = (float)(Eidx[e] - i);
        float ang = d_rel * freq;
        val = (c < 8) ? cosf(ang) : sinf(ang);
    } else {
        int r = c - 16;
        float mu = 20.f * (float)r / 15.f;
        float tt = (Dnb[e] - mu) * (1.f / 1.25f);
        val = expf(-tt * tt);
    }
    feat[(size_t)t] = val;
}

// ---------------- generic SGEMM: C[M,N] = A[M,K]@B[K,N] (+bias)(relu) ----------------
template<int BIAS, int RELU>
__global__ void __launch_bounds__(256)
sgemm_kernel(const float* __restrict__ A, const float* __restrict__ Bm,
             const float* __restrict__ bias, float* __restrict__ C,
             int M, int Nn, int Kk)
{
    constexpr int BM=128, BN=128, BK=8, TM=8, TN=8;
    __shared__ float As[BK][BM];
    __shared__ float Bs[BK][BN];
    int tid = threadIdx.x;
    int cRow = blockIdx.y, cCol = blockIdx.x;
    const float* Ab = A + (size_t)cRow * BM * Kk;
    const float* Bb = Bm + (size_t)cCol * BN;
    int innerRowA = tid >> 1;
    int innerColA = (tid & 1) * 4;
    int innerRowB = tid >> 5;
    int innerColB = (tid & 31) * 4;
    int threadRow = (tid >> 4) * TM;
    int threadCol = (tid & 15) * TN;
    bool aValid = (cRow * BM + innerRowA) < M;

    float acc[TM][TN];
    #pragma unroll
    for (int i2 = 0; i2 < TM; i2++)
        #pragma unroll
        for (int j2 = 0; j2 < TN; j2++) acc[i2][j2] = 0.f;

    for (int k0 = 0; k0 < Kk; k0 += BK) {
        float4 av = aValid ? *(const float4*)(Ab + (size_t)innerRowA * Kk + k0 + innerColA)
                           : make_float4(0.f, 0.f, 0.f, 0.f);
        As[innerColA+0][innerRowA] = av.x;
        As[innerColA+1][innerRowA] = av.y;
        As[innerColA+2][innerRowA] = av.z;
        As[innerColA+3][innerRowA] = av.w;
        float4 bv = *(const float4*)(Bb + (size_t)(k0 + innerRowB) * Nn + innerColB);
        *(float4*)(&Bs[innerRowB][innerColB]) = bv;
        __syncthreads();
        #pragma unroll
        for (int kk = 0; kk < BK; kk++) {
            float4 m0 = *(const float4*)(&As[kk][threadRow]);
            float4 m1 = *(const float4*)(&As[kk][threadRow+4]);
            float4 n0 = *(const float4*)(&Bs[kk][threadCol]);
            float4 n1 = *(const float4*)(&Bs[kk][threadCol+4]);
            float regM[TM] = {m0.x,m0.y,m0.z,m0.w,m1.x,m1.y,m1.z,m1.w};
            float regN[TN] = {n0.x,n0.y,n0.z,n0.w,n1.x,n1.y,n1.z,n1.w};
            #pragma unroll
            for (int i2 = 0; i2 < TM; i2++)
                #pragma unroll
                for (int j2 = 0; j2 < TN; j2++)
                    acc[i2][j2] += regM[i2] * regN[j2];
        }
        __syncthreads();
    }

    float bvals[TN];
    #pragma unroll
    for (int j2 = 0; j2 < TN; j2++)
        bvals[j2] = BIAS ? bias[cCol * BN + threadCol + j2] : 0.f;

    #pragma unroll
    for (int i2 = 0; i2 < TM; i2++) {
        int gr = cRow * BM + threadRow + i2;
        if (gr >= M) break;
        float* Crow = C + (size_t)gr * Nn + cCol * BN + threadCol;
        #pragma unroll
        for (int j2 = 0; j2 < TN; j2 += 4) {
            float4 o;
            o.x = acc[i2][j2+0] + bvals[j2+0];
            o.y = acc[i2][j2+1] + bvals[j2+1];
            o.z = acc[i2][j2+2] + bvals[j2+2];
            o.w = acc[i2][j2+3] + bvals[j2+3];
            if (RELU) { o.x=fmaxf(o.x,0.f); o.y=fmaxf(o.y,0.f); o.z=fmaxf(o.z,0.f); o.w=fmaxf(o.w,0.f); }
            *(float4*)(Crow + j2) = o;
        }
    }
}

// ---------------- qe: qe[n,h,c] = sum_j Q[n,h*32+j] * Wk_top[c, h*32+j] ----------------
__global__ void qe_kernel(const float* __restrict__ Q, const float* __restrict__ Wk_top,
                          float* __restrict__ qe)
{
    int n = blockIdx.x;
    int tid = threadIdx.x;  // 512
    __shared__ float sQ[128];
    if (tid < 128) sQ[tid] = Q[(size_t)n * 128 + tid];
    __syncthreads();
    int h = tid >> 7, c = tid & 127;
    const float* w = Wk_top + (size_t)c * 128 + h * 32;
    const float* q = sQ + h * 32;
    float acc = 0.f;
    #pragma unroll
    for (int j = 0; j < 32; j++) acc += q[j] * w[j];
    qe[((size_t)n * 4 + h) * 128 + c] = acc;
}

// ---------------- fused neighbor attention ----------------
// out[n,d] = sum_k a[h(d),k] * ( (hE[n,k] @ Wv_top)[d] + Vn[idx,d] )
// logits[n,h,k] = ( hE[n,k]·qe[n,h] + q_h·Kn[idx,hslice] ) / sqrt(32)
__global__ void __launch_bounds__(128)
attn_fused_kernel(const float* __restrict__ qe, const float* __restrict__ Q,
                  const float* __restrict__ Kn, const float* __restrict__ Vn,
                  const float* __restrict__ hE, const int* __restrict__ Eidx,
                  const float* __restrict__ mask, const float* __restrict__ Wv_top,
                  float* __restrict__ out)
{
    __shared__ float s_hE[Kc][128];
    __shared__ float s_lg[4][32];
    __shared__ float s_eacc[4][128];
    __shared__ int   s_idx[Kc];
    __shared__ float s_mk[Kc];
    int n = blockIdx.x;
    int tid = threadIdx.x;   // 128
    int h = tid >> 5, lane = tid & 31;
    int b = n / Nc;

    if (tid < Kc) {
        int j = Eidx[(size_t)n * Kc + tid];
        s_idx[tid] = b * Nc + j;
        s_mk[tid]  = mask[(size_t)b * Nc + j];
    }
    // load all hE rows
    #pragma unroll 5
    for (int k = 0; k < Kc; k++)
        s_hE[k][tid] = hE[((size_t)n * Kc + k) * 128 + tid];
    __syncthreads();

    float mi = mask[n];
    float qv = Q[(size_t)n * 128 + tid];        // warp h lane j: q[h*32+j]
    const float* qe_h = qe + ((size_t)n * 4 + h) * 128;
    float qer[4];
    #pragma unroll
    for (int r = 0; r < 4; r++) qer[r] = qe_h[lane + 32 * r];

    // pass 1: logits per head (warp h)
    for (int k = 0; k < Kc; k++) {
        int g = s_idx[k];
        float p = qv * Kn[(size_t)g * 128 + h * 32 + lane];
        #pragma unroll
        for (int r = 0; r < 4; r++) p += s_hE[k][lane + 32 * r] * qer[r];
        #pragma unroll
        for (int o = 16; o > 0; o >>= 1) p += __shfl_xor_sync(0xffffffffu, p, o);
        if (lane == 0) s_lg[h][k] = p * 0.17677669529663687f;  // 1/sqrt(32)
    }
    __syncwarp();
    // softmax per head
    {
        float x = -3.4e38f, mk = 0.f;
        if (lane < Kc) {
            mk = mi * s_mk[lane];
            x = (mk > 0.f) ? s_lg[h][lane] : -3.4028235e38f;
        }
        float mx = x;
        #pragma unroll
        for (int o = 16; o > 0; o >>= 1) mx = fmaxf(mx, __shfl_xor_sync(0xffffffffu, mx, o));
        float ex = (lane < Kc) ? expf(x - mx) : 0.f;
        float sm = ex;
        #pragma unroll
        for (int o = 16; o > 0; o >>= 1) sm += __shfl_xor_sync(0xffffffffu, sm, o);
        if (lane < Kc) s_lg[h][lane] = (ex / sm) * mk;
    }
    __syncthreads();

    // pass 2: accumulate node-V part and weighted hE sums for all heads
    float eacc0 = 0.f, eacc1 = 0.f, eacc2 = 0.f, eacc3 = 0.f;
    float vacc = 0.f;
    for (int k = 0; k < Kc; k++) {
        float he = s_hE[k][tid];
        vacc  += s_lg[h][k] * Vn[(size_t)s_idx[k] * 128 + tid];
        eacc0 += s_lg[0][k] * he;
        eacc1 += s_lg[1][k] * he;
        eacc2 += s_lg[2][k] * he;
        eacc3 += s_lg[3][k] * he;
    }
    s_eacc[0][tid] = eacc0;
    s_eacc[1][tid] = eacc1;
    s_eacc[2][tid] = eacc2;
    s_eacc[3][tid] = eacc3;
    __syncthreads();

    // final: project weighted hE sum through Wv_top column d=tid for head h
    float acc = vacc;
    const float* se = s_eacc[h];
    #pragma unroll 8
    for (int c = 0; c < 128; c++)
        acc += se[c] * Wv_top[(size_t)c * 128 + tid];
    out[(size_t)n * 128 + tid] = acc;
}

// ---------------- layer norm over width 128 (+optional residual, mask) ----------------
__global__ void ln_kernel(const float* __restrict__ x, const float* __restrict__ res,
                          const float* __restrict__ gamma, const float* __restrict__ beta,
                          const float* __restrict__ mask, float* __restrict__ out)
{
    int row = blockIdx.x;
    int c = threadIdx.x;  // 128
    float v = x[(size_t)row * 128 + c];
    if (res) v += res[(size_t)row * 128 + c];
    float s = v, s2 = v * v;
    #pragma unroll
    for (int o = 16; o > 0; o >>= 1) {
        s  += __shfl_xor_sync(0xffffffffu, s,  o);
        s2 += __shfl_xor_sync(0xffffffffu, s2, o);
    }
    __shared__ float ws[4], ws2[4];
    int w = c >> 5;
    if ((c & 31) == 0) { ws[w] = s; ws2[w] = s2; }
    __syncthreads();
    s  = ws[0] + ws[1] + ws[2] + ws[3];
    s2 = ws2[0] + ws2[1] + ws2[2] + ws2[3];
    float mu = s * (1.f / 128.f);
    float var = s2 * (1.f / 128.f) - mu * mu;
    float y = gamma[c] * (v - mu) * rsqrtf(var + 1e-6f) + beta[c];
    if (mask) y *= mask[row];
    out[(size_t)row * 128 + c] = y;
}

// ---------------- final projection ----------------
__global__ void out_kernel(const float* __restrict__ hV, const float* __restrict__ Wout,
                           const float* __restrict__ bout, float* __restrict__ out)
{
    int node = blockIdx.x * 4 + (threadIdx.x >> 5);
    int lane = threadIdx.x & 31;
    if (node >= BNc) return;
    float acc = 0.f;
    #pragma unroll
    for (int m = 0; m < 4; m++)
        acc += hV[(size_t)node * 128 + lane + m * 32] * Wout[lane + m * 32];
    #pragma unroll
    for (int o = 16; o > 0; o >>= 1) acc += __shfl_xor_sync(0xffffffffu, acc, o);
    if (lane == 0) out[node] = acc + bout[0];
}

// ---------------- host launch ----------------
static void* symaddr(const void* sym) { void* p = nullptr; cudaGetSymbolAddress(&p, sym); return p; }

extern "C" void kernel_launch(void* const* d_in, const int* in_sizes, int n_in,
                              void* d_out, int out_size)
{
    const float* X      = (const float*)d_in[0];
    const float* V      = (const float*)d_in[1];
    const float* mask   = (const float*)d_in[2];
    const float* W_v    = (const float*)d_in[3];
    const float* b_v    = (const float*)d_in[4];
    const float* W_e    = (const float*)d_in[5];
    const float* b_e    = (const float*)d_in[6];
    const float* W_edge = (const float*)d_in[7];
    const float* ln_e_g = (const float*)d_in[8];
    const float* ln_e_b = (const float*)d_in[9];
    const float* Wq     = (const float*)d_in[10];
    const float* Wk     = (const float*)d_in[11];
    const float* Wv_a   = (const float*)d_in[12];
    const float* Wo     = (const float*)d_in[13];
    const float* ln1_g  = (const float*)d_in[14];
    const float* ln1_b  = (const float*)d_in[15];
    const float* ln2_g  = (const float*)d_in[16];
    const float* ln2_b  = (const float*)d_in[17];
    const float* W_ff1  = (const float*)d_in[18];
    const float* b_ff1  = (const float*)d_in[19];
    const float* W_ff2  = (const float*)d_in[20];
    const float* b_ff2  = (const float*)d_in[21];
    const float* W_out  = (const float*)d_in[22];
    const float* b_out  = (const float*)d_in[23];
    float* out = (float*)d_out;

    int*   pEidx = (int*)  symaddr(g_Eidx);
    float* pDnb  = (float*)symaddr(g_Dnb);
    float* pFeat = (float*)symaddr(g_feat);
    float* pEtmp = (float*)symaddr(g_Etmp);
    float* phE   = (float*)symaddr(g_hE);
    float* phVa  = (float*)symaddr(g_hVa);
    float* phVb  = (float*)symaddr(g_hVb);
    float* phVm  = (float*)symaddr(g_hVm);
    float* pQ    = (float*)symaddr(g_Q);
    float* pKn   = (float*)symaddr(g_Kn);
    float* pVn   = (float*)symaddr(g_Vn);
    float* pQe   = (float*)symaddr(g_qe);
    float* pAtt  = (float*)symaddr(g_att);
    float* pUpd  = (float*)symaddr(g_upd);
    float* pFF   = (float*)symaddr(g_ff);

    const int gE = (ECNT + 127) / 128;
    const int gN = (BNc + 127) / 128;

    topk_kernel<<<BNc, 256>>>(X, mask, pEidx, pDnb);
    edge_feat_kernel<<<(ECNT * 32 + 255) / 256, 256>>>(pEidx, pDnb, pFeat);
    sgemm_kernel<0,0><<<dim3(1, gE), 256>>>(pFeat, W_edge, nullptr, pEtmp, ECNT, 128, 32);
    ln_kernel<<<ECNT, 128>>>(pEtmp, nullptr, ln_e_g, ln_e_b, nullptr, pEtmp);
    sgemm_kernel<1,0><<<dim3(1, gE), 256>>>(pEtmp, W_e, b_e, phE, ECNT, 128, 128);
    sgemm_kernel<1,0><<<dim3(1, gN), 256>>>(V, W_v, b_v, phVa, BNc, 128, 1024);

    float* cur = phVa;
    float* nxt = phVb;
    for (int l = 0; l < Lc; l++) {
        const float* Wk_l  = Wk   + (size_t)l * 256 * 128;
        const float* Wv_l  = Wv_a + (size_t)l * 256 * 128;
        // node-level projections
        sgemm_kernel<0,0><<<dim3(1, gN), 256>>>(cur, Wq + (size_t)l*128*128, nullptr, pQ,  BNc, 128, 128);
        sgemm_kernel<0,0><<<dim3(1, gN), 256>>>(cur, Wk_l + 128*128,         nullptr, pKn, BNc, 128, 128);
        sgemm_kernel<0,0><<<dim3(1, gN), 256>>>(cur, Wv_l + 128*128,         nullptr, pVn, BNc, 128, 128);
        qe_kernel<<<BNc, 512>>>(pQ, Wk_l, pQe);
        attn_fused_kernel<<<BNc, 128>>>(pQe, pQ, pKn, pVn, phE, pEidx, mask, Wv_l, pAtt);
        sgemm_kernel<0,0><<<dim3(1, gN), 256>>>(pAtt, Wo + (size_t)l*128*128, nullptr, pUpd, BNc, 128, 128);
        ln_kernel<<<BNc, 128>>>(pUpd, cur, ln1_g + l*128, ln1_b + l*128, nullptr, phVm);
        sgemm_kernel<1,1><<<dim3(4, gN), 256>>>(phVm, W_ff1 + (size_t)l*128*512, b_ff1 + l*512, pFF, BNc, 512, 128);
        sgemm_kernel<1,0><<<dim3(1, gN), 256>>>(pFF,  W_ff2 + (size_t)l*512*128, b_ff2 + l*128, pUpd, BNc, 128, 512);
        ln_kernel<<<BNc, 128>>>(pUpd, phVm, ln2_g + l*128, ln2_b + l*128, mask, nxt);
        float* t = cur; cur = nxt; nxt = t;
    }
    out_kernel<<<(BNc + 3) / 4, 128>>>(cur, W_out, b_out, out);
}

// round 3
// speedup vs baseline: 2.3714x; 1.7330x over previous
#include <cuda_runtime.h>
#include <math.h>
#include <stdint.h>

// ---------------- problem constants ----------------
#define Bc 4
#define Nc 1500
#define Kc 30
#define Lc 4
#define BNc (Bc*Nc)          // 6000
#define ECNT (BNc*Kc)        // 180000

// ---------------- device scratch ----------------
__device__ int   g_Eidx[ECNT];
__device__ float g_Dnb[ECNT];
__device__ float g_fs[(size_t)ECNT*32];   // feat/sigma per edge
__device__ float g_ms[ECNT];              // mu/sigma per edge
__device__ float g_hVa[(size_t)BNc*128];
__device__ float g_hVb[(size_t)BNc*128];
__device__ float g_hVm[(size_t)BNc*128];
__device__ float g_Q[(size_t)BNc*128];
__device__ float g_Kn[(size_t)BNc*128];
__device__ float g_Vn[(size_t)BNc*128];
__device__ float g_att[(size_t)BNc*128];
__device__ float g_upd[(size_t)BNc*128];
__device__ float g_ff[(size_t)BNc*512];
// precomputed constants
__device__ float g_Wcomb[32*128];
__device__ float g_G[32*32];
__device__ float g_m[32];
__device__ float g_s[128];
__device__ float g_bp[128];
__device__ float g_At[Lc*4*32*32];   // transposed: At[l][h][j][i]
__device__ float g_sv[Lc*128];
__device__ float g_bv[Lc*128];
__device__ float g_Wcv[Lc*32*128];
__device__ float g_sv2[Lc*128];
__device__ float g_bv2[Lc*128];

__device__ __forceinline__ float wred(float v) {
    #pragma unroll
    for (int o = 16; o > 0; o >>= 1) v += __shfl_xor_sync(0xffffffffu, v, o);
    return v;
}

// ---------------- top-K nearest neighbors ----------------
__global__ void topk_kernel(const float* __restrict__ X, const float* __restrict__ mask,
                            int* __restrict__ Eidx, float* __restrict__ Dnb)
{
    __shared__ float sD[Nc];
    __shared__ float rv[256];
    __shared__ int   ri[256];
    __shared__ float s_rowmax;
    int row = blockIdx.x;
    int b = row / Nc;
    int i = row - b * Nc;
    int tid = threadIdx.x;
    const float* Xb = X + (size_t)b * Nc * 3;
    const float* mb = mask + (size_t)b * Nc;
    float xi0 = Xb[i*3+0], xi1 = Xb[i*3+1], xi2 = Xb[i*3+2];
    float mi = mb[i];
    float lmax = 0.f;
    for (int j = tid; j < Nc; j += 256) {
        float dx = xi0 - Xb[j*3+0];
        float dy = xi1 - Xb[j*3+1];
        float dz = xi2 - Xb[j*3+2];
        float d = sqrtf(dx*dx + dy*dy + dz*dz + 1e-6f);
        float D = mi * mb[j] * d;
        sD[j] = D;
        lmax = fmaxf(lmax, D);
    }
    rv[tid] = lmax;
    __syncthreads();
    for (int s = 128; s > 0; s >>= 1) {
        if (tid < s) rv[tid] = fmaxf(rv[tid], rv[tid+s]);
        __syncthreads();
    }
    if (tid == 0) s_rowmax = rv[0];
    __syncthreads();
    float rowmax = s_rowmax;
    for (int j = tid; j < Nc; j += 256) {
        float m2 = mi * mb[j];
        sD[j] = sD[j] + (1.f - m2) * rowmax;
    }
    __syncthreads();
    for (int sel = 0; sel < Kc; sel++) {
        float bv = 3.3e38f; int bi = 0x7fffffff;
        for (int j = tid; j < Nc; j += 256) {
            float v = sD[j];
            if (v < bv) { bv = v; bi = j; }
        }
        rv[tid] = bv; ri[tid] = bi;
        __syncthreads();
        for (int s = 128; s > 0; s >>= 1) {
            if (tid < s) {
                float ov = rv[tid+s]; int oi = ri[tid+s];
                if (ov < rv[tid] || (ov == rv[tid] && oi < ri[tid])) { rv[tid]=ov; ri[tid]=oi; }
            }
            __syncthreads();
        }
        if (tid == 0) {
            Eidx[(size_t)row*Kc + sel] = ri[0];
            Dnb [(size_t)row*Kc + sel] = rv[0];
            sD[ri[0]] = 3.4e38f;
        }
        __syncthreads();
    }
}

// ---------------- precompute 1: W_comb, G, m, s, bias' ----------------
__global__ void pre1_kernel(const float* __restrict__ W_edge, const float* __restrict__ W_e,
                            const float* __restrict__ lng, const float* __restrict__ lnb,
                            const float* __restrict__ b_e)
{
    int tid = threadIdx.x;
    if (blockIdx.x == 0) {
        if (tid < 128) {
            float s = 0.f, bp = 0.f;
            for (int c = 0; c < 128; c++) {
                float w = W_e[(size_t)c*128 + tid];
                s  += lng[c] * w;
                bp += lnb[c] * w;
            }
            g_s[tid] = s;
            g_bp[tid] = bp + b_e[tid];
        }
    } else if (blockIdx.x == 1) {
        if (tid < 32) {
            float acc = 0.f;
            for (int c = 0; c < 128; c++) acc += W_edge[tid*128 + c];
            g_m[tid] = acc * (1.f/128.f);
        }
        for (int t = tid; t < 1024; t += 256) {
            int i = t >> 5, j = t & 31;
            float acc = 0.f;
            for (int c = 0; c < 128; c++) acc += W_edge[i*128+c] * W_edge[j*128+c];
            g_G[t] = acc;
        }
    } else {
        for (int t = tid; t < 4096; t += 256) {
            int i = t >> 7, d = t & 127;
            float acc = 0.f;
            for (int c = 0; c < 128; c++)
                acc += W_edge[i*128+c] * lng[c] * W_e[(size_t)c*128 + d];
            g_Wcomb[t] = acc;
        }
    }
}

// ---------------- precompute 2 (per layer): At, W_cv, sv, bv, sv2, bv2 ----------------
__global__ void pre2_kernel(const float* __restrict__ Wk, const float* __restrict__ Wv)
{
    int l = blockIdx.x;
    int tid = threadIdx.x;
    const float* Wk_l = Wk + (size_t)l * 256 * 128;  // top rows 0..127
    const float* Wv_l = Wv + (size_t)l * 256 * 128;
    for (int t = tid; t < 4096; t += 256) {
        int h = t >> 10, r = t & 1023, j = r >> 5, i = r & 31;
        float acc = 0.f;
        for (int c = 0; c < 128; c++)
            acc += g_Wcomb[i*128+c] * Wk_l[(size_t)c*128 + h*32 + j];
        g_At[l*4096 + h*1024 + j*32 + i] = acc;   // transposed store
    }
    for (int t = tid; t < 4096; t += 256) {
        int i = t >> 7, d = t & 127;
        float acc = 0.f;
        for (int c = 0; c < 128; c++)
            acc += g_Wcomb[i*128+c] * Wv_l[(size_t)c*128 + d];
        g_Wcv[l*4096 + t] = acc;
    }
    if (tid < 128) {
        float sv = 0.f, bv = 0.f, sv2 = 0.f, bv2 = 0.f;
        for (int c = 0; c < 128; c++) {
            float wk = Wk_l[(size_t)c*128 + tid];
            float wv = Wv_l[(size_t)c*128 + tid];
            sv  += g_s[c]  * wk;
            bv  += g_bp[c] * wk;
            sv2 += g_s[c]  * wv;
            bv2 += g_bp[c] * wv;
        }
        g_sv [l*128 + tid] = sv;
        g_bv [l*128 + tid] = bv;
        g_sv2[l*128 + tid] = sv2;
        g_bv2[l*128 + tid] = bv2;
    }
}

// ---------------- fused edge features -> (feat/sigma, mu/sigma) ----------------
// warp per edge; lane = feature component
__global__ void __launch_bounds__(256)
edge_fs_kernel(const int* __restrict__ Eidx, const float* __restrict__ Dnb,
               float* __restrict__ fs, float* __restrict__ ms)
{
    __shared__ float sG[1024];
    __shared__ float sm[32];
    int tid = threadIdx.x;
    for (int t = tid; t < 1024; t += 256) sG[t] = g_G[t];
    if (tid < 32) sm[tid] = g_m[tid];
    __syncthreads();

    int e = blockIdx.x * 8 + (tid >> 5);
    int c = tid & 31;
    float f;
    if (c < 16) {
        int mdx = c & 7;
        float freq = expf((float)(2*mdx) * (-9.210340371976184f / 16.f));
        int node = e / Kc;
        int i = node % Nc;
        float d_rel = (float)(Eidx[e] - i);
        float ang = d_rel * freq;
        f = (c < 8) ? cosf(ang) : sinf(ang);
    } else {
        int r = c - 16;
        float mu = 20.f * (float)r / 15.f;
        float tt = (Dnb[e] - mu) * (1.f / 1.25f);
        f = expf(-tt * tt);
    }
    float mu = wred(f * sm[c]);
    float gf = 0.f;
    #pragma unroll
    for (int j = 0; j < 32; j++) {
        float fj = __shfl_sync(0xffffffffu, f, j);
        gf += sG[j*32 + c] * fj;   // G symmetric
    }
    float ss = wred(f * gf);
    float var = ss * (1.f/128.f) - mu * mu;
    float inv = rsqrtf(var + 1e-6f);
    fs[(size_t)e*32 + c] = f * inv;
    if (c == 0) ms[e] = mu * inv;
}

// ---------------- generic SGEMM: C[M,N] = A[M,K]@B[K,N] (+bias)(relu) ----------------
template<int BIAS, int RELU>
__global__ void __launch_bounds__(256)
sgemm_kernel(const float* __restrict__ A, const float* __restrict__ Bm,
             const float* __restrict__ bias, float* __restrict__ C,
             int M, int Nn, int Kk)
{
    constexpr int BM=128, BN=128, BK=8, TM=8, TN=8;
    __shared__ float As[BK][BM];
    __shared__ float Bs[BK][BN];
    int tid = threadIdx.x;
    int cRow = blockIdx.y, cCol = blockIdx.x;
    const float* Ab = A + (size_t)cRow * BM * Kk;
    const float* Bb = Bm + (size_t)cCol * BN;
    int innerRowA = tid >> 1;
    int innerColA = (tid & 1) * 4;
    int innerRowB = tid >> 5;
    int innerColB = (tid & 31) * 4;
    int threadRow = (tid >> 4) * TM;
    int threadCol = (tid & 15) * TN;
    bool aValid = (cRow * BM + innerRowA) < M;

    float acc[TM][TN];
    #pragma unroll
    for (int i2 = 0; i2 < TM; i2++)
        #pragma unroll
        for (int j2 = 0; j2 < TN; j2++) acc[i2][j2] = 0.f;

    for (int k0 = 0; k0 < Kk; k0 += BK) {
        float4 av = aValid ? *(const float4*)(Ab + (size_t)innerRowA * Kk + k0 + innerColA)
                           : make_float4(0.f, 0.f, 0.f, 0.f);
        As[innerColA+0][innerRowA] = av.x;
        As[innerColA+1][innerRowA] = av.y;
        As[innerColA+2][innerRowA] = av.z;
        As[innerColA+3][innerRowA] = av.w;
        float4 bv = *(const float4*)(Bb + (size_t)(k0 + innerRowB) * Nn + innerColB);
        *(float4*)(&Bs[innerRowB][innerColB]) = bv;
        __syncthreads();
        #pragma unroll
        for (int kk = 0; kk < BK; kk++) {
            float4 m0 = *(const float4*)(&As[kk][threadRow]);
            float4 m1 = *(const float4*)(&As[kk][threadRow+4]);
            float4 n0 = *(const float4*)(&Bs[kk][threadCol]);
            float4 n1 = *(const float4*)(&Bs[kk][threadCol+4]);
            float regM[TM] = {m0.x,m0.y,m0.z,m0.w,m1.x,m1.y,m1.z,m1.w};
            float regN[TN] = {n0.x,n0.y,n0.z,n0.w,n1.x,n1.y,n1.z,n1.w};
            #pragma unroll
            for (int i2 = 0; i2 < TM; i2++)
                #pragma unroll
                for (int j2 = 0; j2 < TN; j2++)
                    acc[i2][j2] += regM[i2] * regN[j2];
        }
        __syncthreads();
    }

    float bvals[TN];
    #pragma unroll
    for (int j2 = 0; j2 < TN; j2++)
        bvals[j2] = BIAS ? bias[cCol * BN + threadCol + j2] : 0.f;

    #pragma unroll
    for (int i2 = 0; i2 < TM; i2++) {
        int gr = cRow * BM + threadRow + i2;
        if (gr >= M) break;
        float* Crow = C + (size_t)gr * Nn + cCol * BN + threadCol;
        #pragma unroll
        for (int j2 = 0; j2 < TN; j2 += 4) {
            float4 o;
            o.x = acc[i2][j2+0] + bvals[j2+0];
            o.y = acc[i2][j2+1] + bvals[j2+1];
            o.z = acc[i2][j2+2] + bvals[j2+2];
            o.w = acc[i2][j2+3] + bvals[j2+3];
            if (RELU) { o.x=fmaxf(o.x,0.f); o.y=fmaxf(o.y,0.f); o.z=fmaxf(o.z,0.f); o.w=fmaxf(o.w,0.f); }
            *(float4*)(Crow + j2) = o;
        }
    }
}

// ---------------- fused Q/Kn/Vn GEMM (3 weights, 3 outputs, N=K=128) ----------------
__global__ void __launch_bounds__(256)
sgemm_qkv_kernel(const float* __restrict__ A,
                 const float* __restrict__ B0, const float* __restrict__ B1, const float* __restrict__ B2,
                 float* __restrict__ C0, float* __restrict__ C1, float* __restrict__ C2, int M)
{
    constexpr int BM=128, BK=8, TM=8, TN=8;
    const float* Bm = (blockIdx.x == 0) ? B0 : (blockIdx.x == 1) ? B1 : B2;
    float* C = (blockIdx.x == 0) ? C0 : (blockIdx.x == 1) ? C1 : C2;
    __shared__ float As[BK][BM];
    __shared__ float Bs[BK][128];
    int tid = threadIdx.x;
    int cRow = blockIdx.y;
    const float* Ab = A + (size_t)cRow * BM * 128;
    int innerRowA = tid >> 1;
    int innerColA = (tid & 1) * 4;
    int innerRowB = tid >> 5;
    int innerColB = (tid & 31) * 4;
    int threadRow = (tid >> 4) * TM;
    int threadCol = (tid & 15) * TN;
    bool aValid = (cRow * BM + innerRowA) < M;

    float acc[TM][TN];
    #pragma unroll
    for (int i2 = 0; i2 < TM; i2++)
        #pragma unroll
        for (int j2 = 0; j2 < TN; j2++) acc[i2][j2] = 0.f;

    for (int k0 = 0; k0 < 128; k0 += BK) {
        float4 av = aValid ? *(const float4*)(Ab + (size_t)innerRowA * 128 + k0 + innerColA)
                           : make_float4(0.f, 0.f, 0.f, 0.f);
        As[innerColA+0][innerRowA] = av.x;
        As[innerColA+1][innerRowA] = av.y;
        As[innerColA+2][innerRowA] = av.z;
        As[innerColA+3][innerRowA] = av.w;
        float4 bv = *(const float4*)(Bm + (size_t)(k0 + innerRowB) * 128 + innerColB);
        *(float4*)(&Bs[innerRowB][innerColB]) = bv;
        __syncthreads();
        #pragma unroll
        for (int kk = 0; kk < BK; kk++) {
            float4 m0 = *(const float4*)(&As[kk][threadRow]);
            float4 m1 = *(const float4*)(&As[kk][threadRow+4]);
            float4 n0 = *(const float4*)(&Bs[kk][threadCol]);
            float4 n1 = *(const float4*)(&Bs[kk][threadCol+4]);
            float regM[TM] = {m0.x,m0.y,m0.z,m0.w,m1.x,m1.y,m1.z,m1.w};
            float regN[TN] = {n0.x,n0.y,n0.z,n0.w,n1.x,n1.y,n1.z,n1.w};
            #pragma unroll
            for (int i2 = 0; i2 < TM; i2++)
                #pragma unroll
                for (int j2 = 0; j2 < TN; j2++)
                    acc[i2][j2] += regM[i2] * regN[j2];
        }
        __syncthreads();
    }
    #pragma unroll
    for (int i2 = 0; i2 < TM; i2++) {
        int gr = cRow * BM + threadRow + i2;
        if (gr >= M) break;
        float* Crow = C + (size_t)gr * 128 + threadCol;
        #pragma unroll
        for (int j2 = 0; j2 < TN; j2 += 4) {
            float4 o;
            o.x = acc[i2][j2+0]; o.y = acc[i2][j2+1];
            o.z = acc[i2][j2+2]; o.w = acc[i2][j2+3];
            *(float4*)(Crow + j2) = o;
        }
    }
}

// ---------------- fused neighbor attention (rank-33 h_E) ----------------
__global__ void __launch_bounds__(128)
attn2_kernel(const float* __restrict__ Q, const float* __restrict__ Kn, const float* __restrict__ Vn,
             const float* __restrict__ fs, const float* __restrict__ ms,
             const int* __restrict__ Eidx, const float* __restrict__ mask,
             int l, float* __restrict__ out)
{
    __shared__ float sKnT[128*31];
    __shared__ float sVn[Kc][128];
    __shared__ float sfs[Kc*33];
    __shared__ float sq[128];
    __shared__ float sQe2[4][32];
    __shared__ float sa[4][32];
    __shared__ float sfa[4][32];
    __shared__ float sms_[Kc], smk[Kc];
    __shared__ int   sidx[Kc];
    __shared__ float sma[4], ssa[4];

    int n = blockIdx.x;
    int tid = threadIdx.x;
    int h = tid >> 5, lane = tid & 31;
    int b = n / Nc;

    if (tid < Kc) {
        int j = Eidx[(size_t)n*Kc + tid];
        sidx[tid] = b * Nc + j;
        smk[tid]  = mask[(size_t)b*Nc + j];
        sms_[tid] = ms[(size_t)n*Kc + tid];
    }
    sq[tid] = Q[(size_t)n*128 + tid];
    __syncthreads();

    for (int k = 0; k < Kc; k++) {
        int g = sidx[k];
        sKnT[tid*31 + k] = Kn[(size_t)g*128 + tid];
        sVn[k][tid]      = Vn[(size_t)g*128 + tid];
    }
    for (int t = tid; t < Kc*32; t += 128) {
        int k = t >> 5, c = t & 31;
        sfs[k*33 + c] = fs[((size_t)n*Kc + k)*32 + c];
    }

    // per-head scalars + Qe2 (warp-local)
    float qh = sq[h*32 + lane];
    const float* sv_l  = g_sv  + l*128;
    const float* bv_l  = g_bv  + l*128;
    float sqv = wred(qh * sv_l[h*32 + lane]);
    float bqv = wred(qh * bv_l[h*32 + lane]);
    const float* Ath = g_At + l*4096 + h*1024;
    float qe2 = 0.f;
    #pragma unroll
    for (int j = 0; j < 32; j++) {
        float qj = __shfl_sync(0xffffffffu, qh, j);
        qe2 += Ath[j*32 + lane] * qj;
    }
    sQe2[h][lane] = qe2;
    __syncthreads();

    // logits (lane = neighbor k)
    float mi = mask[n];
    float a = 0.f;
    {
        float x = -3.4028235e38f, mk = 0.f;
        if (lane < Kc) {
            mk = mi * smk[lane];
            float acc = bqv - sms_[lane] * sqv;
            #pragma unroll
            for (int i = 0; i < 32; i++)
                acc += sfs[lane*33 + i] * sQe2[h][i];
            #pragma unroll
            for (int j = 0; j < 32; j++)
                acc += sKnT[(h*32 + j)*31 + lane] * sq[h*32 + j];
            acc *= 0.17677669529663687f;
            x = (mk > 0.f) ? acc : -3.4028235e38f;
        }
        float mx = x;
        #pragma unroll
        for (int o = 16; o > 0; o >>= 1) mx = fmaxf(mx, __shfl_xor_sync(0xffffffffu, mx, o));
        float ex = (lane < Kc) ? expf(x - mx) : 0.f;
        float sm = wred(ex);
        a = (lane < Kc) ? (ex / sm) * mk : 0.f;
        sa[h][lane] = a;
    }
    float sa_tot = wred(a);
    float ma_tot = wred((lane < Kc) ? a * sms_[lane] : 0.f);
    if (lane == 0) { ssa[h] = sa_tot; sma[h] = ma_tot; }
    __syncwarp();

    // fa[i] = sum_k a_k * fs_k[i]  (lane = i)
    float fa = 0.f;
    #pragma unroll 6
    for (int k = 0; k < Kc; k++)
        fa += sa[h][k] * sfs[k*33 + lane];
    sfa[h][lane] = fa;
    __syncthreads();

    // output (thread = feature d)
    float vacc = 0.f;
    #pragma unroll 6
    for (int k = 0; k < Kc; k++)
        vacc += sa[h][k] * sVn[k][tid];
    const float* Wcv_l = g_Wcv + l*4096;
    float ed = 0.f;
    #pragma unroll 8
    for (int i = 0; i < 32; i++)
        ed += sfa[h][i] * Wcv_l[i*128 + tid];
    out[(size_t)n*128 + tid] = vacc + ed - sma[h] * g_sv2[l*128 + tid] + ssa[h] * g_bv2[l*128 + tid];
}

// ---------------- layer norm over width 128 ----------------
__global__ void ln_kernel(const float* __restrict__ x, const float* __restrict__ res,
                          const float* __restrict__ gamma, const float* __restrict__ beta,
                          const float* __restrict__ mask, float* __restrict__ out)
{
    int row = blockIdx.x;
    int c = threadIdx.x;  // 128
    float v = x[(size_t)row * 128 + c];
    if (res) v += res[(size_t)row * 128 + c];
    float s = v, s2 = v * v;
    #pragma unroll
    for (int o = 16; o > 0; o >>= 1) {
        s  += __shfl_xor_sync(0xffffffffu, s,  o);
        s2 += __shfl_xor_sync(0xffffffffu, s2, o);
    }
    __shared__ float ws[4], ws2[4];
    int w = c >> 5;
    if ((c & 31) == 0) { ws[w] = s; ws2[w] = s2; }
    __syncthreads();
    s  = ws[0] + ws[1] + ws[2] + ws[3];
    s2 = ws2[0] + ws2[1] + ws2[2] + ws2[3];
    float mu = s * (1.f / 128.f);
    float var = s2 * (1.f / 128.f) - mu * mu;
    float y = gamma[c] * (v - mu) * rsqrtf(var + 1e-6f) + beta[c];
    if (mask) y *= mask[row];
    out[(size_t)row * 128 + c] = y;
}

// ---------------- final projection ----------------
__global__ void out_kernel(const float* __restrict__ hV, const float* __restrict__ Wout,
                           const float* __restrict__ bout, float* __restrict__ out)
{
    int node = blockIdx.x * 4 + (threadIdx.x >> 5);
    int lane = threadIdx.x & 31;
    if (node >= BNc) return;
    float acc = 0.f;
    #pragma unroll
    for (int m = 0; m < 4; m++)
        acc += hV[(size_t)node * 128 + lane + m * 32] * Wout[lane + m * 32];
    #pragma unroll
    for (int o = 16; o > 0; o >>= 1) acc += __shfl_xor_sync(0xffffffffu, acc, o);
    if (lane == 0) out[node] = acc + bout[0];
}

// ---------------- host launch ----------------
static void* symaddr(const void* sym) { void* p = nullptr; cudaGetSymbolAddress(&p, sym); return p; }

extern "C" void kernel_launch(void* const* d_in, const int* in_sizes, int n_in,
                              void* d_out, int out_size)
{
    const float* X      = (const float*)d_in[0];
    const float* V      = (const float*)d_in[1];
    const float* mask   = (const float*)d_in[2];
    const float* W_v    = (const float*)d_in[3];
    const float* b_v    = (const float*)d_in[4];
    const float* W_e    = (const float*)d_in[5];
    const float* b_e    = (const float*)d_in[6];
    const float* W_edge = (const float*)d_in[7];
    const float* ln_e_g = (const float*)d_in[8];
    const float* ln_e_b = (const float*)d_in[9];
    const float* Wq     = (const float*)d_in[10];
    const float* Wk     = (const float*)d_in[11];
    const float* Wv_a   = (const float*)d_in[12];
    const float* Wo     = (const float*)d_in[13];
    const float* ln1_g  = (const float*)d_in[14];
    const float* ln1_b  = (const float*)d_in[15];
    const float* ln2_g  = (const float*)d_in[16];
    const float* ln2_b  = (const float*)d_in[17];
    const float* W_ff1  = (const float*)d_in[18];
    const float* b_ff1  = (const float*)d_in[19];
    const float* W_ff2  = (const float*)d_in[20];
    const float* b_ff2  = (const float*)d_in[21];
    const float* W_out  = (const float*)d_in[22];
    const float* b_out  = (const float*)d_in[23];
    float* out = (float*)d_out;

    int*   pEidx = (int*)  symaddr(g_Eidx);
    float* pDnb  = (float*)symaddr(g_Dnb);
    float* pFs   = (float*)symaddr(g_fs);
    float* pMs   = (float*)symaddr(g_ms);
    float* phVa  = (float*)symaddr(g_hVa);
    float* phVb  = (float*)symaddr(g_hVb);
    float* phVm  = (float*)symaddr(g_hVm);
    float* pQ    = (float*)symaddr(g_Q);
    float* pKn   = (float*)symaddr(g_Kn);
    float* pVn   = (float*)symaddr(g_Vn);
    float* pAtt  = (float*)symaddr(g_att);
    float* pUpd  = (float*)symaddr(g_upd);
    float* pFF   = (float*)symaddr(g_ff);

    const int gN = (BNc + 127) / 128;   // 47

    topk_kernel<<<BNc, 256>>>(X, mask, pEidx, pDnb);
    pre1_kernel<<<3, 256>>>(W_edge, W_e, ln_e_g, ln_e_b, b_e);
    pre2_kernel<<<Lc, 256>>>(Wk, Wv_a);
    edge_fs_kernel<<<ECNT/8, 256>>>(pEidx, pDnb, pFs, pMs);
    sgemm_kernel<1,0><<<dim3(1, gN), 256>>>(V, W_v, b_v, phVa, BNc, 128, 1024);

    float* cur = phVa;
    float* nxt = phVb;
    for (int l = 0; l < Lc; l++) {
        const float* Wk_bot = Wk   + (size_t)l*256*128 + 128*128;
        const float* Wv_bot = Wv_a + (size_t)l*256*128 + 128*128;
        sgemm_qkv_kernel<<<dim3(3, gN), 256>>>(cur, Wq + (size_t)l*128*128, Wk_bot, Wv_bot,
                                               pQ, pKn, pVn, BNc);
        attn2_kernel<<<BNc, 128>>>(pQ, pKn, pVn, pFs, pMs, pEidx, mask, l, pAtt);
        sgemm_kernel<0,0><<<dim3(1, gN), 256>>>(pAtt, Wo + (size_t)l*128*128, nullptr, pUpd, BNc, 128, 128);
        ln_kernel<<<BNc, 128>>>(pUpd, cur, ln1_g + l*128, ln1_b + l*128, nullptr, phVm);
        sgemm_kernel<1,1><<<dim3(4, gN), 256>>>(phVm, W_ff1 + (size_t)l*128*512, b_ff1 + l*512, pFF, BNc, 512, 128);
        sgemm_kernel<1,0><<<dim3(1, gN), 256>>>(pFF,  W_ff2 + (size_t)l*512*128, b_ff2 + l*128, pUpd, BNc, 128, 512);
        ln_kernel<<<BNc, 128>>>(pUpd, phVm, ln2_g + l*128, ln2_b + l*128, mask, nxt);
        float* t = cur; cur = nxt; nxt = t;
    }
    out_kernel<<<(BNc + 3) / 4, 128>>>(cur, W_out, b_out, out);
}

// round 4
// speedup vs baseline: 2.3949x; 1.0099x over previous
#include <cuda_runtime.h>
#include <math.h>
#include <stdint.h>

// ---------------- problem constants ----------------
#define Bc 4
#define Nc 1500
#define Kc 30
#define Lc 4
#define BNc (Bc*Nc)          // 6000
#define ECNT (BNc*Kc)        // 180000

// ---------------- device scratch ----------------
__device__ int   g_Eidx[ECNT];
__device__ float g_Dnb[ECNT];
__device__ float g_fs[(size_t)ECNT*32];
__device__ float g_ms[ECNT];
__device__ float g_hVa[(size_t)BNc*128];
__device__ float g_hVb[(size_t)BNc*128];
__device__ float g_hVm[(size_t)BNc*128];
__device__ float g_Q[(size_t)BNc*128];
__device__ float g_Kn[(size_t)BNc*128];
__device__ float g_Vn[(size_t)BNc*128];
__device__ float g_ff[(size_t)BNc*512];
// precomputed constants
__device__ float g_Wcomb[32*128];
__device__ float g_G[32*32];
__device__ float g_m[32];
__device__ float g_s[128];
__device__ float g_bp[128];
__device__ float g_At[Lc*4*32*32];
__device__ float g_sv[Lc*128];
__device__ float g_bv[Lc*128];
__device__ float g_Wcv[Lc*32*128];
__device__ float g_sv2[Lc*128];
__device__ float g_bv2[Lc*128];

__device__ __forceinline__ float wred(float v) {
    #pragma unroll
    for (int o = 16; o > 0; o >>= 1) v += __shfl_xor_sync(0xffffffffu, v, o);
    return v;
}

// ---------------- top-K nearest neighbors ----------------
__global__ void topk_kernel(const float* __restrict__ X, const float* __restrict__ mask,
                            int* __restrict__ Eidx, float* __restrict__ Dnb)
{
    __shared__ float sD[Nc];
    __shared__ float rv[256];
    __shared__ int   ri[256];
    __shared__ float s_rowmax;
    int row = blockIdx.x;
    int b = row / Nc;
    int i = row - b * Nc;
    int tid = threadIdx.x;
    const float* Xb = X + (size_t)b * Nc * 3;
    const float* mb = mask + (size_t)b * Nc;
    float xi0 = Xb[i*3+0], xi1 = Xb[i*3+1], xi2 = Xb[i*3+2];
    float mi = mb[i];
    float lmax = 0.f;
    for (int j = tid; j < Nc; j += 256) {
        float dx = xi0 - Xb[j*3+0];
        float dy = xi1 - Xb[j*3+1];
        float dz = xi2 - Xb[j*3+2];
        float d = sqrtf(dx*dx + dy*dy + dz*dz + 1e-6f);
        float D = mi * mb[j] * d;
        sD[j] = D;
        lmax = fmaxf(lmax, D);
    }
    rv[tid] = lmax;
    __syncthreads();
    for (int s = 128; s > 0; s >>= 1) {
        if (tid < s) rv[tid] = fmaxf(rv[tid], rv[tid+s]);
        __syncthreads();
    }
    if (tid == 0) s_rowmax = rv[0];
    __syncthreads();
    float rowmax = s_rowmax;
    for (int j = tid; j < Nc; j += 256) {
        float m2 = mi * mb[j];
        sD[j] = sD[j] + (1.f - m2) * rowmax;
    }
    __syncthreads();
    for (int sel = 0; sel < Kc; sel++) {
        float bv = 3.3e38f; int bi = 0x7fffffff;
        for (int j = tid; j < Nc; j += 256) {
            float v = sD[j];
            if (v < bv) { bv = v; bi = j; }
        }
        rv[tid] = bv; ri[tid] = bi;
        __syncthreads();
        for (int s = 128; s > 0; s >>= 1) {
            if (tid < s) {
                float ov = rv[tid+s]; int oi = ri[tid+s];
                if (ov < rv[tid] || (ov == rv[tid] && oi < ri[tid])) { rv[tid]=ov; ri[tid]=oi; }
            }
            __syncthreads();
        }
        if (tid == 0) {
            Eidx[(size_t)row*Kc + sel] = ri[0];
            Dnb [(size_t)row*Kc + sel] = rv[0];
            sD[ri[0]] = 3.4e38f;
        }
        __syncthreads();
    }
}

// ---------------- precompute 1 ----------------
__global__ void pre1_kernel(const float* __restrict__ W_edge, const float* __restrict__ W_e,
                            const float* __restrict__ lng, const float* __restrict__ lnb,
                            const float* __restrict__ b_e)
{
    int tid = threadIdx.x;
    if (blockIdx.x == 0) {
        if (tid < 128) {
            float s = 0.f, bp = 0.f;
            for (int c = 0; c < 128; c++) {
                float w = W_e[(size_t)c*128 + tid];
                s  += lng[c] * w;
                bp += lnb[c] * w;
            }
            g_s[tid] = s;
            g_bp[tid] = bp + b_e[tid];
        }
    } else if (blockIdx.x == 1) {
        if (tid < 32) {
            float acc = 0.f;
            for (int c = 0; c < 128; c++) acc += W_edge[tid*128 + c];
            g_m[tid] = acc * (1.f/128.f);
        }
        for (int t = tid; t < 1024; t += 256) {
            int i = t >> 5, j = t & 31;
            float acc = 0.f;
            for (int c = 0; c < 128; c++) acc += W_edge[i*128+c] * W_edge[j*128+c];
            g_G[t] = acc;
        }
    } else {
        for (int t = tid; t < 4096; t += 256) {
            int i = t >> 7, d = t & 127;
            float acc = 0.f;
            for (int c = 0; c < 128; c++)
                acc += W_edge[i*128+c] * lng[c] * W_e[(size_t)c*128 + d];
            g_Wcomb[t] = acc;
        }
    }
}

// ---------------- precompute 2 ----------------
__global__ void pre2_kernel(const float* __restrict__ Wk, const float* __restrict__ Wv)
{
    int l = blockIdx.x;
    int tid = threadIdx.x;
    const float* Wk_l = Wk + (size_t)l * 256 * 128;
    const float* Wv_l = Wv + (size_t)l * 256 * 128;
    for (int t = tid; t < 4096; t += 256) {
        int h = t >> 10, r = t & 1023, j = r >> 5, i = r & 31;
        float acc = 0.f;
        for (int c = 0; c < 128; c++)
            acc += g_Wcomb[i*128+c] * Wk_l[(size_t)c*128 + h*32 + j];
        g_At[l*4096 + h*1024 + j*32 + i] = acc;
    }
    for (int t = tid; t < 4096; t += 256) {
        int i = t >> 7, d = t & 127;
        float acc = 0.f;
        for (int c = 0; c < 128; c++)
            acc += g_Wcomb[i*128+c] * Wv_l[(size_t)c*128 + d];
        g_Wcv[l*4096 + t] = acc;
    }
    if (tid < 128) {
        float sv = 0.f, bv = 0.f, sv2 = 0.f, bv2 = 0.f;
        for (int c = 0; c < 128; c++) {
            float wk = Wk_l[(size_t)c*128 + tid];
            float wv = Wv_l[(size_t)c*128 + tid];
            sv  += g_s[c]  * wk;
            bv  += g_bp[c] * wk;
            sv2 += g_s[c]  * wv;
            bv2 += g_bp[c] * wv;
        }
        g_sv [l*128 + tid] = sv;
        g_bv [l*128 + tid] = bv;
        g_sv2[l*128 + tid] = sv2;
        g_bv2[l*128 + tid] = bv2;
    }
}

// ---------------- fused edge features -> (feat/sigma, mu/sigma) ----------------
__global__ void __launch_bounds__(256)
edge_fs_kernel(const int* __restrict__ Eidx, const float* __restrict__ Dnb,
               float* __restrict__ fs, float* __restrict__ ms)
{
    __shared__ float sG[1024];
    __shared__ float sm[32];
    int tid = threadIdx.x;
    for (int t = tid; t < 1024; t += 256) sG[t] = g_G[t];
    if (tid < 32) sm[tid] = g_m[tid];
    __syncthreads();

    int e = blockIdx.x * 8 + (tid >> 5);
    int c = tid & 31;
    float f;
    if (c < 16) {
        int mdx = c & 7;
        float freq = expf((float)(2*mdx) * (-9.210340371976184f / 16.f));
        int node = e / Kc;
        int i = node % Nc;
        float d_rel = (float)(Eidx[e] - i);
        float ang = d_rel * freq;
        f = (c < 8) ? cosf(ang) : sinf(ang);
    } else {
        int r = c - 16;
        float mu = 20.f * (float)r / 15.f;
        float tt = (Dnb[e] - mu) * (1.f / 1.25f);
        f = expf(-tt * tt);
    }
    float mu = wred(f * sm[c]);
    float gf = 0.f;
    #pragma unroll
    for (int j = 0; j < 32; j++) {
        float fj = __shfl_sync(0xffffffffu, f, j);
        gf += sG[j*32 + c] * fj;
    }
    float ss = wred(f * gf);
    float var = ss * (1.f/128.f) - mu * mu;
    float inv = rsqrtf(var + 1e-6f);
    fs[(size_t)e*32 + c] = f * inv;
    if (c == 0) ms[e] = mu * inv;
}

// ---------------- generic tiled SGEMM (256 threads) ----------------
template<int BM, int BN, int TM, int TN, int BIAS, int RELU>
__global__ void __launch_bounds__(256)
sgemm_t(const float* __restrict__ A, const float* __restrict__ Bm,
        const float* __restrict__ bias, float* __restrict__ C,
        int M, int Nn, int Kk)
{
    __shared__ float As[8][BM];
    __shared__ float Bs[8][BN];
    int tid = threadIdx.x;
    int cRow = blockIdx.y, cCol = blockIdx.x;
    const float* Ab = A + (size_t)cRow * BM * Kk;
    const float* Bb = Bm + cCol * BN;
    constexpr int NT = BN / TN;
    int threadRow = (tid / NT) * TM;
    int threadCol = (tid % NT) * TN;

    float acc[TM][TN];
    #pragma unroll
    for (int i = 0; i < TM; i++)
        #pragma unroll
        for (int j = 0; j < TN; j++) acc[i][j] = 0.f;

    for (int k0 = 0; k0 < Kk; k0 += 8) {
        #pragma unroll
        for (int t = tid; t < BM*8; t += 256) {
            int r = t >> 3, c = t & 7;
            int gr = cRow * BM + r;
            As[c][r] = (gr < M) ? Ab[(size_t)r*Kk + k0 + c] : 0.f;
        }
        #pragma unroll
        for (int t = tid; t < 8*BN; t += 256) {
            int r = t / BN, c = t % BN;
            Bs[r][c] = Bb[(size_t)(k0 + r) * Nn + c];
        }
        __syncthreads();
        #pragma unroll
        for (int kk = 0; kk < 8; kk++) {
            float regM[TM], regN[TN];
            #pragma unroll
            for (int i = 0; i < TM; i++) regM[i] = As[kk][threadRow + i];
            #pragma unroll
            for (int j = 0; j < TN; j++) regN[j] = Bs[kk][threadCol + j];
            #pragma unroll
            for (int i = 0; i < TM; i++)
                #pragma unroll
                for (int j = 0; j < TN; j++)
                    acc[i][j] += regM[i] * regN[j];
        }
        __syncthreads();
    }

    float bvals[TN];
    #pragma unroll
    for (int j = 0; j < TN; j++)
        bvals[j] = BIAS ? bias[cCol * BN + threadCol + j] : 0.f;

    #pragma unroll
    for (int i = 0; i < TM; i++) {
        int gr = cRow * BM + threadRow + i;
        if (gr >= M) break;
        float* Crow = C + (size_t)gr * Nn + cCol * BN + threadCol;
        #pragma unroll
        for (int j = 0; j < TN; j += 4) {
            float4 o;
            o.x = acc[i][j+0] + bvals[j+0];
            o.y = acc[i][j+1] + bvals[j+1];
            o.z = acc[i][j+2] + bvals[j+2];
            o.w = acc[i][j+3] + bvals[j+3];
            if (RELU) { o.x=fmaxf(o.x,0.f); o.y=fmaxf(o.y,0.f); o.z=fmaxf(o.z,0.f); o.w=fmaxf(o.w,0.f); }
            *(float4*)(Crow + j) = o;
        }
    }
}

// ---------------- ff2 GEMM + bias + residual + LN2 + mask (BM=64,BN=128,TM=4,TN=8) ----------------
__global__ void __launch_bounds__(256)
sgemm_ln_kernel(const float* __restrict__ A, const float* __restrict__ Bm,
                const float* __restrict__ bias, const float* __restrict__ res,
                const float* __restrict__ gamma, const float* __restrict__ beta,
                const float* __restrict__ mask, float* __restrict__ C,
                int M, int Kk)
{
    constexpr int BM=64, TM=4, TN=8;
    __shared__ float As[8][BM];
    __shared__ float Bs[8][128];
    int tid = threadIdx.x;
    int cRow = blockIdx.y;
    const float* Ab = A + (size_t)cRow * BM * Kk;
    int threadRow = (tid >> 4) * TM;
    int threadCol = (tid & 15) * TN;

    float acc[TM][TN];
    #pragma unroll
    for (int i = 0; i < TM; i++)
        #pragma unroll
        for (int j = 0; j < TN; j++) acc[i][j] = 0.f;

    for (int k0 = 0; k0 < Kk; k0 += 8) {
        #pragma unroll
        for (int t = tid; t < BM*8; t += 256) {
            int r = t >> 3, c = t & 7;
            int gr = cRow * BM + r;
            As[c][r] = (gr < M) ? Ab[(size_t)r*Kk + k0 + c] : 0.f;
        }
        #pragma unroll
        for (int t = tid; t < 1024; t += 256) {
            int r = t >> 7, c = t & 127;
            Bs[r][c] = Bm[(size_t)(k0 + r) * 128 + c];
        }
        __syncthreads();
        #pragma unroll
        for (int kk = 0; kk < 8; kk++) {
            float regM[TM], regN[TN];
            #pragma unroll
            for (int i = 0; i < TM; i++) regM[i] = As[kk][threadRow + i];
            #pragma unroll
            for (int j = 0; j < TN; j++) regN[j] = Bs[kk][threadCol + j];
            #pragma unroll
            for (int i = 0; i < TM; i++)
                #pragma unroll
                for (int j = 0; j < TN; j++)
                    acc[i][j] += regM[i] * regN[j];
        }
        __syncthreads();
    }

    float bvals[TN], gv[TN], bev[TN];
    #pragma unroll
    for (int j = 0; j < TN; j++) {
        bvals[j] = bias[threadCol + j];
        gv[j]    = gamma[threadCol + j];
        bev[j]   = beta[threadCol + j];
    }

    #pragma unroll
    for (int i = 0; i < TM; i++) {
        int gr = cRow * BM + threadRow + i;
        bool valid = gr < M;
        // v = gemm + bias + residual
        float s = 0.f, s2 = 0.f;
        #pragma unroll
        for (int j = 0; j < TN; j++) {
            float v = acc[i][j] + bvals[j];
            if (valid) v += res[(size_t)gr * 128 + threadCol + j];
            acc[i][j] = v;
            s += v; s2 += v * v;
        }
        // reduce over the 16 threads (contiguous lanes) owning this row
        #pragma unroll
        for (int o = 8; o > 0; o >>= 1) {
            s  += __shfl_xor_sync(0xffffffffu, s,  o);
            s2 += __shfl_xor_sync(0xffffffffu, s2, o);
        }
        if (!valid) continue;
        float mu = s * (1.f/128.f);
        float var = s2 * (1.f/128.f) - mu * mu;
        float inv = rsqrtf(var + 1e-6f);
        float mk = mask[gr];
        float* Crow = C + (size_t)gr * 128 + threadCol;
        #pragma unroll
        for (int j = 0; j < TN; j += 4) {
            float4 o;
            o.x = mk * (gv[j+0] * (acc[i][j+0] - mu) * inv + bev[j+0]);
            o.y = mk * (gv[j+1] * (acc[i][j+1] - mu) * inv + bev[j+1]);
            o.z = mk * (gv[j+2] * (acc[i][j+2] - mu) * inv + bev[j+2]);
            o.w = mk * (gv[j+3] * (acc[i][j+3] - mu) * inv + bev[j+3]);
            *(float4*)(Crow + j) = o;
        }
    }
}

// ---------------- fused Q/Kn/Vn GEMM ----------------
__global__ void __launch_bounds__(256)
sgemm_qkv_kernel(const float* __restrict__ A,
                 const float* __restrict__ B0, const float* __restrict__ B1, const float* __restrict__ B2,
                 float* __restrict__ C0, float* __restrict__ C1, float* __restrict__ C2, int M)
{
    constexpr int BM=128, BK=8, TM=8, TN=8;
    const float* Bm = (blockIdx.x == 0) ? B0 : (blockIdx.x == 1) ? B1 : B2;
    float* C = (blockIdx.x == 0) ? C0 : (blockIdx.x == 1) ? C1 : C2;
    __shared__ float As[BK][BM];
    __shared__ float Bs[BK][128];
    int tid = threadIdx.x;
    int cRow = blockIdx.y;
    const float* Ab = A + (size_t)cRow * BM * 128;
    int innerRowA = tid >> 1;
    int innerColA = (tid & 1) * 4;
    int innerRowB = tid >> 5;
    int innerColB = (tid & 31) * 4;
    int threadRow = (tid >> 4) * TM;
    int threadCol = (tid & 15) * TN;
    bool aValid = (cRow * BM + innerRowA) < M;

    float acc[TM][TN];
    #pragma unroll
    for (int i2 = 0; i2 < TM; i2++)
        #pragma unroll
        for (int j2 = 0; j2 < TN; j2++) acc[i2][j2] = 0.f;

    for (int k0 = 0; k0 < 128; k0 += BK) {
        float4 av = aValid ? *(const float4*)(Ab + (size_t)innerRowA * 128 + k0 + innerColA)
                           : make_float4(0.f, 0.f, 0.f, 0.f);
        As[innerColA+0][innerRowA] = av.x;
        As[innerColA+1][innerRowA] = av.y;
        As[innerColA+2][innerRowA] = av.z;
        As[innerColA+3][innerRowA] = av.w;
        float4 bv = *(const float4*)(Bm + (size_t)(k0 + innerRowB) * 128 + innerColB);
        *(float4*)(&Bs[innerRowB][innerColB]) = bv;
        __syncthreads();
        #pragma unroll
        for (int kk = 0; kk < BK; kk++) {
            float4 m0 = *(const float4*)(&As[kk][threadRow]);
            float4 m1 = *(const float4*)(&As[kk][threadRow+4]);
            float4 n0 = *(const float4*)(&Bs[kk][threadCol]);
            float4 n1 = *(const float4*)(&Bs[kk][threadCol+4]);
            float regM[TM] = {m0.x,m0.y,m0.z,m0.w,m1.x,m1.y,m1.z,m1.w};
            float regN[TN] = {n0.x,n0.y,n0.z,n0.w,n1.x,n1.y,n1.z,n1.w};
            #pragma unroll
            for (int i2 = 0; i2 < TM; i2++)
                #pragma unroll
                for (int j2 = 0; j2 < TN; j2++)
                    acc[i2][j2] += regM[i2] * regN[j2];
        }
        __syncthreads();
    }
    #pragma unroll
    for (int i2 = 0; i2 < TM; i2++) {
        int gr = cRow * BM + threadRow + i2;
        if (gr >= M) break;
        float* Crow = C + (size_t)gr * 128 + threadCol;
        #pragma unroll
        for (int j2 = 0; j2 < TN; j2 += 4) {
            float4 o;
            o.x = acc[i2][j2+0]; o.y = acc[i2][j2+1];
            o.z = acc[i2][j2+2]; o.w = acc[i2][j2+3];
            *(float4*)(Crow + j2) = o;
        }
    }
}

// ---------------- fused neighbor attention + Wo + residual + LN1 ----------------
__global__ void __launch_bounds__(128)
attn3_kernel(const float* __restrict__ Q, const float* __restrict__ Kn, const float* __restrict__ Vn,
             const float* __restrict__ fs, const float* __restrict__ ms,
             const int* __restrict__ Eidx, const float* __restrict__ mask,
             int l, const float* __restrict__ Wo_l, const float* __restrict__ res,
             const float* __restrict__ gamma, const float* __restrict__ beta,
             float* __restrict__ out)
{
    __shared__ float sKnT[128*31];
    __shared__ float sVn[Kc][128];
    __shared__ float sfs[Kc*33];
    __shared__ float sq[128];
    __shared__ float sQe2[4][32];
    __shared__ float sa[4][32];
    __shared__ float sfa[4][32];
    __shared__ float sms_[Kc], smk[Kc];
    __shared__ int   sidx[Kc];
    __shared__ float sma[4], ssa[4];
    __shared__ float satt[128];
    __shared__ float ws[4], ws2[4];

    int n = blockIdx.x;
    int tid = threadIdx.x;
    int h = tid >> 5, lane = tid & 31;
    int b = n / Nc;

    if (tid < Kc) {
        int j = Eidx[(size_t)n*Kc + tid];
        sidx[tid] = b * Nc + j;
        smk[tid]  = mask[(size_t)b*Nc + j];
        sms_[tid] = ms[(size_t)n*Kc + tid];
    }
    sq[tid] = Q[(size_t)n*128 + tid];
    __syncthreads();

    for (int k = 0; k < Kc; k++) {
        int g = sidx[k];
        sKnT[tid*31 + k] = Kn[(size_t)g*128 + tid];
        sVn[k][tid]      = Vn[(size_t)g*128 + tid];
    }
    for (int t = tid; t < Kc*32; t += 128) {
        int k = t >> 5, c = t & 31;
        sfs[k*33 + c] = fs[((size_t)n*Kc + k)*32 + c];
    }

    float qh = sq[h*32 + lane];
    const float* sv_l  = g_sv  + l*128;
    const float* bv_l  = g_bv  + l*128;
    float sqv = wred(qh * sv_l[h*32 + lane]);
    float bqv = wred(qh * bv_l[h*32 + lane]);
    const float* Ath = g_At + l*4096 + h*1024;
    float qe2 = 0.f;
    #pragma unroll
    for (int j = 0; j < 32; j++) {
        float qj = __shfl_sync(0xffffffffu, qh, j);
        qe2 += Ath[j*32 + lane] * qj;
    }
    sQe2[h][lane] = qe2;
    __syncthreads();

    float mi = mask[n];
    float a = 0.f;
    {
        float x = -3.4028235e38f, mk = 0.f;
        if (lane < Kc) {
            mk = mi * smk[lane];
            float acc = bqv - sms_[lane] * sqv;
            #pragma unroll
            for (int i = 0; i < 32; i++)
                acc += sfs[lane*33 + i] * sQe2[h][i];
            #pragma unroll
            for (int j = 0; j < 32; j++)
                acc += sKnT[(h*32 + j)*31 + lane] * sq[h*32 + j];
            acc *= 0.17677669529663687f;
            x = (mk > 0.f) ? acc : -3.4028235e38f;
        }
        float mx = x;
        #pragma unroll
        for (int o = 16; o > 0; o >>= 1) mx = fmaxf(mx, __shfl_xor_sync(0xffffffffu, mx, o));
        float ex = (lane < Kc) ? expf(x - mx) : 0.f;
        float sm = wred(ex);
        a = (lane < Kc) ? (ex / sm) * mk : 0.f;
        sa[h][lane] = a;
    }
    float sa_tot = wred(a);
    float ma_tot = wred((lane < Kc) ? a * sms_[lane] : 0.f);
    if (lane == 0) { ssa[h] = sa_tot; sma[h] = ma_tot; }
    __syncwarp();

    float fa = 0.f;
    #pragma unroll 6
    for (int k = 0; k < Kc; k++)
        fa += sa[h][k] * sfs[k*33 + lane];
    sfa[h][lane] = fa;
    __syncthreads();

    float vacc = 0.f;
    #pragma unroll 6
    for (int k = 0; k < Kc; k++)
        vacc += sa[h][k] * sVn[k][tid];
    const float* Wcv_l = g_Wcv + l*4096;
    float ed = 0.f;
    #pragma unroll 8
    for (int i = 0; i < 32; i++)
        ed += sfa[h][i] * Wcv_l[i*128 + tid];
    float od = vacc + ed - sma[h] * g_sv2[l*128 + tid] + ssa[h] * g_bv2[l*128 + tid];

    // ---- Wo projection + residual + LN1 ----
    satt[tid] = od;
    __syncthreads();
    float y = res[(size_t)n*128 + tid];
    #pragma unroll 8
    for (int c = 0; c < 128; c++)
        y += satt[c] * Wo_l[(size_t)c*128 + tid];

    float s = y, s2 = y * y;
    #pragma unroll
    for (int o = 16; o > 0; o >>= 1) {
        s  += __shfl_xor_sync(0xffffffffu, s,  o);
        s2 += __shfl_xor_sync(0xffffffffu, s2, o);
    }
    if (lane == 0) { ws[h] = s; ws2[h] = s2; }
    __syncthreads();
    s  = ws[0] + ws[1] + ws[2] + ws[3];
    s2 = ws2[0] + ws2[1] + ws2[2] + ws2[3];
    float mu = s * (1.f/128.f);
    float var = s2 * (1.f/128.f) - mu * mu;
    out[(size_t)n*128 + tid] = gamma[tid] * (y - mu) * rsqrtf(var + 1e-6f) + beta[tid];
}

// ---------------- final projection ----------------
__global__ void out_kernel(const float* __restrict__ hV, const float* __restrict__ Wout,
                           const float* __restrict__ bout, float* __restrict__ out)
{
    int node = blockIdx.x * 4 + (threadIdx.x >> 5);
    int lane = threadIdx.x & 31;
    if (node >= BNc) return;
    float acc = 0.f;
    #pragma unroll
    for (int m = 0; m < 4; m++)
        acc += hV[(size_t)node * 128 + lane + m * 32] * Wout[lane + m * 32];
    #pragma unroll
    for (int o = 16; o > 0; o >>= 1) acc += __shfl_xor_sync(0xffffffffu, acc, o);
    if (lane == 0) out[node] = acc + bout[0];
}

// ---------------- host launch ----------------
static void* symaddr(const void* sym) { void* p = nullptr; cudaGetSymbolAddress(&p, sym); return p; }

extern "C" void kernel_launch(void* const* d_in, const int* in_sizes, int n_in,
                              void* d_out, int out_size)
{
    const float* X      = (const float*)d_in[0];
    const float* V      = (const float*)d_in[1];
    const float* mask   = (const float*)d_in[2];
    const float* W_v    = (const float*)d_in[3];
    const float* b_v    = (const float*)d_in[4];
    const float* W_e    = (const float*)d_in[5];
    const float* b_e    = (const float*)d_in[6];
    const float* W_edge = (const float*)d_in[7];
    const float* ln_e_g = (const float*)d_in[8];
    const float* ln_e_b = (const float*)d_in[9];
    const float* Wq     = (const float*)d_in[10];
    const float* Wk     = (const float*)d_in[11];
    const float* Wv_a   = (const float*)d_in[12];
    const float* Wo     = (const float*)d_in[13];
    const float* ln1_g  = (const float*)d_in[14];
    const float* ln1_b  = (const float*)d_in[15];
    const float* ln2_g  = (const float*)d_in[16];
    const float* ln2_b  = (const float*)d_in[17];
    const float* W_ff1  = (const float*)d_in[18];
    const float* b_ff1  = (const float*)d_in[19];
    const float* W_ff2  = (const float*)d_in[20];
    const float* b_ff2  = (const float*)d_in[21];
    const float* W_out  = (const float*)d_in[22];
    const float* b_out  = (const float*)d_in[23];
    float* out = (float*)d_out;

    int*   pEidx = (int*)  symaddr(g_Eidx);
    float* pDnb  = (float*)symaddr(g_Dnb);
    float* pFs   = (float*)symaddr(g_fs);
    float* pMs   = (float*)symaddr(g_ms);
    float* phVa  = (float*)symaddr(g_hVa);
    float* phVb  = (float*)symaddr(g_hVb);
    float* phVm  = (float*)symaddr(g_hVm);
    float* pQ    = (float*)symaddr(g_Q);
    float* pKn   = (float*)symaddr(g_Kn);
    float* pVn   = (float*)symaddr(g_Vn);
    float* pFF   = (float*)symaddr(g_ff);

    const int gN128 = (BNc + 127) / 128;  // 47
    const int gN64  = (BNc + 63) / 64;    // 94

    topk_kernel<<<BNc, 256>>>(X, mask, pEidx, pDnb);
    pre1_kernel<<<3, 256>>>(W_edge, W_e, ln_e_g, ln_e_b, b_e);
    pre2_kernel<<<Lc, 256>>>(Wk, Wv_a);
    edge_fs_kernel<<<ECNT/8, 256>>>(pEidx, pDnb, pFs, pMs);
    // h_V = V @ W_v + b_v : 64x64 tiles for SM utilization
    sgemm_t<64,64,4,4,1,0><<<dim3(2, gN64), 256>>>(V, W_v, b_v, phVa, BNc, 128, 1024);

    float* cur = phVa;
    float* nxt = phVb;
    for (int l = 0; l < Lc; l++) {
        const float* Wk_bot = Wk   + (size_t)l*256*128 + 128*128;
        const float* Wv_bot = Wv_a + (size_t)l*256*128 + 128*128;
        sgemm_qkv_kernel<<<dim3(3, gN128), 256>>>(cur, Wq + (size_t)l*128*128, Wk_bot, Wv_bot,
                                                  pQ, pKn, pVn, BNc);
        attn3_kernel<<<BNc, 128>>>(pQ, pKn, pVn, pFs, pMs, pEidx, mask, l,
                                   Wo + (size_t)l*128*128, cur,
                                   ln1_g + l*128, ln1_b + l*128, phVm);
        sgemm_t<64,128,4,8,1,1><<<dim3(4, gN64), 256>>>(phVm, W_ff1 + (size_t)l*128*512,
                                                        b_ff1 + l*512, pFF, BNc, 512, 128);
        sgemm_ln_kernel<<<dim3(1, gN64), 256>>>(pFF, W_ff2 + (size_t)l*512*128, b_ff2 + l*128,
                                                phVm, ln2_g + l*128, ln2_b + l*128, mask,
                                                nxt, BNc, 512);
        float* t = cur; cur = nxt; nxt = t;
    }
    out_kernel<<<(BNc + 3) / 4, 128>>>(cur, W_out, b_out, out);
}

// round 5
// speedup vs baseline: 2.8360x; 1.1842x over previous
#include <cuda_runtime.h>
#include <math.h>
#include <stdint.h>

// ---------------- problem constants ----------------
#define Bc 4
#define Nc 1500
#define Kc 30
#define Lc 4
#define BNc (Bc*Nc)          // 6000
#define ECNT (BNc*Kc)        // 180000
#define SEG 188              // 8*188 >= 1500

// ---------------- device scratch ----------------
__device__ int   g_Eidx[ECNT];
__device__ float g_Dnb[ECNT];
__device__ float g_fs[(size_t)ECNT*32];
__device__ float g_ms[ECNT];
__device__ float g_hVa[(size_t)BNc*128];
__device__ float g_hVb[(size_t)BNc*128];
__device__ float g_hVm[(size_t)BNc*128];
__device__ float g_Q[(size_t)BNc*128];
__device__ float g_Kn[(size_t)BNc*128];
__device__ float g_Vn[(size_t)BNc*128];
__device__ float g_ff[(size_t)BNc*512];
// precomputed constants
__device__ float g_Wcomb[32*128];
__device__ float g_G[32*32];
__device__ float g_m[32];
__device__ float g_s[128];
__device__ float g_bp[128];
__device__ float g_At[Lc*4*32*32];
__device__ float g_sv[Lc*128];
__device__ float g_bv[Lc*128];
__device__ float g_Wcv[Lc*32*128];
__device__ float g_sv2[Lc*128];
__device__ float g_bv2[Lc*128];

__device__ __forceinline__ float wred(float v) {
    #pragma unroll
    for (int o = 16; o > 0; o >>= 1) v += __shfl_xor_sync(0xffffffffu, v, o);
    return v;
}

// ---------------- top-K nearest neighbors (segmented rescan) ----------------
__global__ void __launch_bounds__(256)
topk_kernel(const float* __restrict__ X, const float* __restrict__ mask,
            int* __restrict__ Eidx, float* __restrict__ Dnb)
{
    __shared__ float sD[Nc];
    __shared__ float wmin[8];
    __shared__ int   widx[8];
    __shared__ float red8[8];
    __shared__ float s_rowmax;
    __shared__ int   s_win;
    int row = blockIdx.x;
    int b = row / Nc;
    int i = row - b * Nc;
    int tid = threadIdx.x;
    int warp = tid >> 5, lane = tid & 31;
    const float* Xb = X + (size_t)b * Nc * 3;
    const float* mb = mask + (size_t)b * Nc;
    float xi0 = Xb[i*3+0], xi1 = Xb[i*3+1], xi2 = Xb[i*3+2];
    float mi = mb[i];
    float lmax = 0.f;
    for (int j = tid; j < Nc; j += 256) {
        float dx = xi0 - Xb[j*3+0];
        float dy = xi1 - Xb[j*3+1];
        float dz = xi2 - Xb[j*3+2];
        float d = sqrtf(dx*dx + dy*dy + dz*dz + 1e-6f);
        float D = mi * mb[j] * d;
        sD[j] = D;
        lmax = fmaxf(lmax, D);
    }
    #pragma unroll
    for (int o = 16; o > 0; o >>= 1) lmax = fmaxf(lmax, __shfl_xor_sync(0xffffffffu, lmax, o));
    if (lane == 0) red8[warp] = lmax;
    __syncthreads();
    if (tid == 0) {
        float m = red8[0];
        #pragma unroll
        for (int w = 1; w < 8; w++) m = fmaxf(m, red8[w]);
        s_rowmax = m;
    }
    __syncthreads();
    float rowmax = s_rowmax;
    for (int j = tid; j < Nc; j += 256) {
        float m2 = mi * mb[j];
        sD[j] = sD[j] + (1.f - m2) * rowmax;
    }
    __syncthreads();

    // per-warp segment minima
    int s0 = warp * SEG;
    int s1 = min(Nc, s0 + SEG);
    {
        float v = 3.4e38f; int vi = 0x7fffffff;
        for (int j = s0 + lane; j < s1; j += 32) {
            float x = sD[j];
            if (x < v) { v = x; vi = j; }
        }
        #pragma unroll
        for (int o = 16; o > 0; o >>= 1) {
            float ov = __shfl_xor_sync(0xffffffffu, v, o);
            int   oi = __shfl_xor_sync(0xffffffffu, vi, o);
            if (ov < v || (ov == v && oi < vi)) { v = ov; vi = oi; }
        }
        if (lane == 0) { wmin[warp] = v; widx[warp] = vi; }
    }
    __syncthreads();

    for (int sel = 0; sel < Kc; sel++) {
        if (warp == 0) {
            float v = (lane < 8) ? wmin[lane] : 3.4e38f;
            int  vi = (lane < 8) ? widx[lane] : 0x7fffffff;
            #pragma unroll
            for (int o = 4; o > 0; o >>= 1) {
                float ov = __shfl_xor_sync(0xffffffffu, v, o);
                int   oi = __shfl_xor_sync(0xffffffffu, vi, o);
                if (ov < v || (ov == v && oi < vi)) { v = ov; vi = oi; }
            }
            if (lane == 0) {
                Eidx[(size_t)row*Kc + sel] = vi;
                Dnb [(size_t)row*Kc + sel] = v;
                sD[vi] = 3.4e38f;
                s_win = vi / SEG;
            }
        }
        __syncthreads();
        if (warp == s_win) {
            float v = 3.4e38f; int vi = 0x7fffffff;
            for (int j = s0 + lane; j < s1; j += 32) {
                float x = sD[j];
                if (x < v) { v = x; vi = j; }
            }
            #pragma unroll
            for (int o = 16; o > 0; o >>= 1) {
                float ov = __shfl_xor_sync(0xffffffffu, v, o);
                int   oi = __shfl_xor_sync(0xffffffffu, vi, o);
                if (ov < v || (ov == v && oi < vi)) { v = ov; vi = oi; }
            }
            if (lane == 0) { wmin[warp] = v; widx[warp] = vi; }
        }
        __syncthreads();
    }
}

// ---------------- precompute 1 ----------------
__global__ void pre1_kernel(const float* __restrict__ W_edge, const float* __restrict__ W_e,
                            const float* __restrict__ lng, const float* __restrict__ lnb,
                            const float* __restrict__ b_e)
{
    int tid = threadIdx.x;
    if (blockIdx.x == 0) {
        if (tid < 128) {
            float s = 0.f, bp = 0.f;
            for (int c = 0; c < 128; c++) {
                float w = W_e[(size_t)c*128 + tid];
                s  += lng[c] * w;
                bp += lnb[c] * w;
            }
            g_s[tid] = s;
            g_bp[tid] = bp + b_e[tid];
        }
    } else if (blockIdx.x == 1) {
        if (tid < 32) {
            float acc = 0.f;
            for (int c = 0; c < 128; c++) acc += W_edge[tid*128 + c];
            g_m[tid] = acc * (1.f/128.f);
        }
        for (int t = tid; t < 1024; t += 256) {
            int i = t >> 5, j = t & 31;
            float acc = 0.f;
            for (int c = 0; c < 128; c++) acc += W_edge[i*128+c] * W_edge[j*128+c];
            g_G[t] = acc;
        }
    } else {
        for (int t = tid; t < 4096; t += 256) {
            int i = t >> 7, d = t & 127;
            float acc = 0.f;
            for (int c = 0; c < 128; c++)
                acc += W_edge[i*128+c] * lng[c] * W_e[(size_t)c*128 + d];
            g_Wcomb[t] = acc;
        }
    }
}

// ---------------- precompute 2 ----------------
__global__ void pre2_kernel(const float* __restrict__ Wk, const float* __restrict__ Wv)
{
    int l = blockIdx.x;
    int tid = threadIdx.x;
    const float* Wk_l = Wk + (size_t)l * 256 * 128;
    const float* Wv_l = Wv + (size_t)l * 256 * 128;
    for (int t = tid; t < 4096; t += 256) {
        int h = t >> 10, r = t & 1023, j = r >> 5, i = r & 31;
        float acc = 0.f;
        for (int c = 0; c < 128; c++)
            acc += g_Wcomb[i*128+c] * Wk_l[(size_t)c*128 + h*32 + j];
        g_At[l*4096 + h*1024 + j*32 + i] = acc;
    }
    for (int t = tid; t < 4096; t += 256) {
        int i = t >> 7, d = t & 127;
        float acc = 0.f;
        for (int c = 0; c < 128; c++)
            acc += g_Wcomb[i*128+c] * Wv_l[(size_t)c*128 + d];
        g_Wcv[l*4096 + t] = acc;
    }
    if (tid < 128) {
        float sv = 0.f, bv = 0.f, sv2 = 0.f, bv2 = 0.f;
        for (int c = 0; c < 128; c++) {
            float wk = Wk_l[(size_t)c*128 + tid];
            float wv = Wv_l[(size_t)c*128 + tid];
            sv  += g_s[c]  * wk;
            bv  += g_bp[c] * wk;
            sv2 += g_s[c]  * wv;
            bv2 += g_bp[c] * wv;
        }
        g_sv [l*128 + tid] = sv;
        g_bv [l*128 + tid] = bv;
        g_sv2[l*128 + tid] = sv2;
        g_bv2[l*128 + tid] = bv2;
    }
}

// ---------------- fused edge features -> (feat/sigma, mu/sigma) ----------------
__global__ void __launch_bounds__(256)
edge_fs_kernel(const int* __restrict__ Eidx, const float* __restrict__ Dnb,
               float* __restrict__ fs, float* __restrict__ ms)
{
    __shared__ float sG[1024];
    __shared__ float sm[32];
    int tid = threadIdx.x;
    for (int t = tid; t < 1024; t += 256) sG[t] = g_G[t];
    if (tid < 32) sm[tid] = g_m[tid];
    __syncthreads();

    int e = blockIdx.x * 8 + (tid >> 5);
    int c = tid & 31;
    float f;
    if (c < 16) {
        int mdx = c & 7;
        float freq = expf((float)(2*mdx) * (-9.210340371976184f / 16.f));
        int node = e / Kc;
        int i = node % Nc;
        float d_rel = (float)(Eidx[e] - i);
        float ang = d_rel * freq;
        f = (c < 8) ? cosf(ang) : sinf(ang);
    } else {
        int r = c - 16;
        float mu = 20.f * (float)r / 15.f;
        float tt = (Dnb[e] - mu) * (1.f / 1.25f);
        f = expf(-tt * tt);
    }
    float mu = wred(f * sm[c]);
    float gf = 0.f;
    #pragma unroll
    for (int j = 0; j < 32; j++) {
        float fj = __shfl_sync(0xffffffffu, f, j);
        gf += sG[j*32 + c] * fj;
    }
    float ss = wred(f * gf);
    float var = ss * (1.f/128.f) - mu * mu;
    float inv = rsqrtf(var + 1e-6f);
    fs[(size_t)e*32 + c] = f * inv;
    if (c == 0) ms[e] = mu * inv;
}

// ---------------- generic tiled SGEMM (256 threads) ----------------
template<int BM, int BN, int TM, int TN, int BIAS, int RELU>
__global__ void __launch_bounds__(256)
sgemm_t(const float* __restrict__ A, const float* __restrict__ Bm,
        const float* __restrict__ bias, float* __restrict__ C,
        int M, int Nn, int Kk)
{
    __shared__ float As[8][BM];
    __shared__ float Bs[8][BN];
    int tid = threadIdx.x;
    int cRow = blockIdx.y, cCol = blockIdx.x;
    const float* Ab = A + (size_t)cRow * BM * Kk;
    const float* Bb = Bm + cCol * BN;
    constexpr int NT = BN / TN;
    int threadRow = (tid / NT) * TM;
    int threadCol = (tid % NT) * TN;

    float acc[TM][TN];
    #pragma unroll
    for (int i = 0; i < TM; i++)
        #pragma unroll
        for (int j = 0; j < TN; j++) acc[i][j] = 0.f;

    for (int k0 = 0; k0 < Kk; k0 += 8) {
        #pragma unroll
        for (int t = tid; t < BM*8; t += 256) {
            int r = t >> 3, c = t & 7;
            int gr = cRow * BM + r;
            As[c][r] = (gr < M) ? Ab[(size_t)r*Kk + k0 + c] : 0.f;
        }
        #pragma unroll
        for (int t = tid; t < 8*BN; t += 256) {
            int r = t / BN, c = t % BN;
            Bs[r][c] = Bb[(size_t)(k0 + r) * Nn + c];
        }
        __syncthreads();
        #pragma unroll
        for (int kk = 0; kk < 8; kk++) {
            float regM[TM], regN[TN];
            #pragma unroll
            for (int i = 0; i < TM; i++) regM[i] = As[kk][threadRow + i];
            #pragma unroll
            for (int j = 0; j < TN; j++) regN[j] = Bs[kk][threadCol + j];
            #pragma unroll
            for (int i = 0; i < TM; i++)
                #pragma unroll
                for (int j = 0; j < TN; j++)
                    acc[i][j] += regM[i] * regN[j];
        }
        __syncthreads();
    }

    float bvals[TN];
    #pragma unroll
    for (int j = 0; j < TN; j++)
        bvals[j] = BIAS ? bias[cCol * BN + threadCol + j] : 0.f;

    #pragma unroll
    for (int i = 0; i < TM; i++) {
        int gr = cRow * BM + threadRow + i;
        if (gr >= M) break;
        float* Crow = C + (size_t)gr * Nn + cCol * BN + threadCol;
        #pragma unroll
        for (int j = 0; j < TN; j += 4) {
            float4 o;
            o.x = acc[i][j+0] + bvals[j+0];
            o.y = acc[i][j+1] + bvals[j+1];
            o.z = acc[i][j+2] + bvals[j+2];
            o.w = acc[i][j+3] + bvals[j+3];
            if (RELU) { o.x=fmaxf(o.x,0.f); o.y=fmaxf(o.y,0.f); o.z=fmaxf(o.z,0.f); o.w=fmaxf(o.w,0.f); }
            *(float4*)(Crow + j) = o;
        }
    }
}

// ---------------- ff2 GEMM + bias + residual + LN2 + mask ----------------
__global__ void __launch_bounds__(256)
sgemm_ln_kernel(const float* __restrict__ A, const float* __restrict__ Bm,
                const float* __restrict__ bias, const float* __restrict__ res,
                const float* __restrict__ gamma, const float* __restrict__ beta,
                const float* __restrict__ mask, float* __restrict__ C,
                int M, int Kk)
{
    constexpr int BM=64, TM=4, TN=8;
    __shared__ float As[8][BM];
    __shared__ float Bs[8][128];
    int tid = threadIdx.x;
    int cRow = blockIdx.y;
    const float* Ab = A + (size_t)cRow * BM * Kk;
    int threadRow = (tid >> 4) * TM;
    int threadCol = (tid & 15) * TN;

    float acc[TM][TN];
    #pragma unroll
    for (int i = 0; i < TM; i++)
        #pragma unroll
        for (int j = 0; j < TN; j++) acc[i][j] = 0.f;

    for (int k0 = 0; k0 < Kk; k0 += 8) {
        #pragma unroll
        for (int t = tid; t < BM*8; t += 256) {
            int r = t >> 3, c = t & 7;
            int gr = cRow * BM + r;
            As[c][r] = (gr < M) ? Ab[(size_t)r*Kk + k0 + c] : 0.f;
        }
        #pragma unroll
        for (int t = tid; t < 1024; t += 256) {
            int r = t >> 7, c = t & 127;
            Bs[r][c] = Bm[(size_t)(k0 + r) * 128 + c];
        }
        __syncthreads();
        #pragma unroll
        for (int kk = 0; kk < 8; kk++) {
            float regM[TM], regN[TN];
            #pragma unroll
            for (int i = 0; i < TM; i++) regM[i] = As[kk][threadRow + i];
            #pragma unroll
            for (int j = 0; j < TN; j++) regN[j] = Bs[kk][threadCol + j];
            #pragma unroll
            for (int i = 0; i < TM; i++)
                #pragma unroll
                for (int j = 0; j < TN; j++)
                    acc[i][j] += regM[i] * regN[j];
        }
        __syncthreads();
    }

    float bvals[TN], gv[TN], bev[TN];
    #pragma unroll
    for (int j = 0; j < TN; j++) {
        bvals[j] = bias[threadCol + j];
        gv[j]    = gamma[threadCol + j];
        bev[j]   = beta[threadCol + j];
    }

    #pragma unroll
    for (int i = 0; i < TM; i++) {
        int gr = cRow * BM + threadRow + i;
        bool valid = gr < M;
        float s = 0.f, s2 = 0.f;
        #pragma unroll
        for (int j = 0; j < TN; j++) {
            float v = acc[i][j] + bvals[j];
            if (valid) v += res[(size_t)gr * 128 + threadCol + j];
            acc[i][j] = v;
            s += v; s2 += v * v;
        }
        #pragma unroll
        for (int o = 8; o > 0; o >>= 1) {
            s  += __shfl_xor_sync(0xffffffffu, s,  o);
            s2 += __shfl_xor_sync(0xffffffffu, s2, o);
        }
        if (!valid) continue;
        float mu = s * (1.f/128.f);
        float var = s2 * (1.f/128.f) - mu * mu;
        float inv = rsqrtf(var + 1e-6f);
        float mk = mask[gr];
        float* Crow = C + (size_t)gr * 128 + threadCol;
        #pragma unroll
        for (int j = 0; j < TN; j += 4) {
            float4 o;
            o.x = mk * (gv[j+0] * (acc[i][j+0] - mu) * inv + bev[j+0]);
            o.y = mk * (gv[j+1] * (acc[i][j+1] - mu) * inv + bev[j+1]);
            o.z = mk * (gv[j+2] * (acc[i][j+2] - mu) * inv + bev[j+2]);
            o.w = mk * (gv[j+3] * (acc[i][j+3] - mu) * inv + bev[j+3]);
            *(float4*)(Crow + j) = o;
        }
    }
}

// ---------------- fused Q/Kn/Vn GEMM ----------------
__global__ void __launch_bounds__(256)
sgemm_qkv_kernel(const float* __restrict__ A,
                 const float* __restrict__ B0, const float* __restrict__ B1, const float* __restrict__ B2,
                 float* __restrict__ C0, float* __restrict__ C1, float* __restrict__ C2, int M)
{
    constexpr int BM=128, BK=8, TM=8, TN=8;
    const float* Bm = (blockIdx.x == 0) ? B0 : (blockIdx.x == 1) ? B1 : B2;
    float* C = (blockIdx.x == 0) ? C0 : (blockIdx.x == 1) ? C1 : C2;
    __shared__ float As[BK][BM];
    __shared__ float Bs[BK][128];
    int tid = threadIdx.x;
    int cRow = blockIdx.y;
    const float* Ab = A + (size_t)cRow * BM * 128;
    int innerRowA = tid >> 1;
    int innerColA = (tid & 1) * 4;
    int innerRowB = tid >> 5;
    int innerColB = (tid & 31) * 4;
    int threadRow = (tid >> 4) * TM;
    int threadCol = (tid & 15) * TN;
    bool aValid = (cRow * BM + innerRowA) < M;

    float acc[TM][TN];
    #pragma unroll
    for (int i2 = 0; i2 < TM; i2++)
        #pragma unroll
        for (int j2 = 0; j2 < TN; j2++) acc[i2][j2] = 0.f;

    for (int k0 = 0; k0 < 128; k0 += BK) {
        float4 av = aValid ? *(const float4*)(Ab + (size_t)innerRowA * 128 + k0 + innerColA)
                           : make_float4(0.f, 0.f, 0.f, 0.f);
        As[innerColA+0][innerRowA] = av.x;
        As[innerColA+1][innerRowA] = av.y;
        As[innerColA+2][innerRowA] = av.z;
        As[innerColA+3][innerRowA] = av.w;
        float4 bv = *(const float4*)(Bm + (size_t)(k0 + innerRowB) * 128 + innerColB);
        *(float4*)(&Bs[innerRowB][innerColB]) = bv;
        __syncthreads();
        #pragma unroll
        for (int kk = 0; kk < BK; kk++) {
            float4 m0 = *(const float4*)(&As[kk][threadRow]);
            float4 m1 = *(const float4*)(&As[kk][threadRow+4]);
            float4 n0 = *(const float4*)(&Bs[kk][threadCol]);
            float4 n1 = *(const float4*)(&Bs[kk][threadCol+4]);
            float regM[TM] = {m0.x,m0.y,m0.z,m0.w,m1.x,m1.y,m1.z,m1.w};
            float regN[TN] = {n0.x,n0.y,n0.z,n0.w,n1.x,n1.y,n1.z,n1.w};
            #pragma unroll
            for (int i2 = 0; i2 < TM; i2++)
                #pragma unroll
                for (int j2 = 0; j2 < TN; j2++)
                    acc[i2][j2] += regM[i2] * regN[j2];
        }
        __syncthreads();
    }
    #pragma unroll
    for (int i2 = 0; i2 < TM; i2++) {
        int gr = cRow * BM + threadRow + i2;
        if (gr >= M) break;
        float* Crow = C + (size_t)gr * 128 + threadCol;
        #pragma unroll
        for (int j2 = 0; j2 < TN; j2 += 4) {
            float4 o;
            o.x = acc[i2][j2+0]; o.y = acc[i2][j2+1];
            o.z = acc[i2][j2+2]; o.w = acc[i2][j2+3];
            *(float4*)(Crow + j2) = o;
        }
    }
}

// ---------------- fused neighbor attention + Wo + residual + LN1 (low smem) ----------------
__global__ void __launch_bounds__(128)
attn4_kernel(const float* __restrict__ Q, const float* __restrict__ Kn, const float* __restrict__ Vn,
             const float* __restrict__ fs, const float* __restrict__ ms,
             const int* __restrict__ Eidx, const float* __restrict__ mask,
             int l, const float* __restrict__ Wo_l, const float* __restrict__ res,
             const float* __restrict__ gamma, const float* __restrict__ beta,
             float* __restrict__ out)
{
    __shared__ float sq[128];
    __shared__ float sfs[Kc*33];
    __shared__ float sqk[4][32];
    __shared__ float sQe2[4][32];
    __shared__ float sa[4][32];
    __shared__ float sfa[4][32];
    __shared__ float sms_[Kc], smk[Kc];
    __shared__ int   sidx[Kc];
    __shared__ float sma[4], ssa[4];
    __shared__ float satt[128];
    __shared__ float ws[4], ws2[4];

    int n = blockIdx.x;
    int tid = threadIdx.x;
    int h = tid >> 5, lane = tid & 31;
    int b = n / Nc;

    if (tid < Kc) {
        int j = Eidx[(size_t)n*Kc + tid];
        sidx[tid] = b * Nc + j;
        smk[tid]  = mask[(size_t)b*Nc + j];
        sms_[tid] = ms[(size_t)n*Kc + tid];
    }
    sq[tid] = Q[(size_t)n*128 + tid];
    for (int t = tid; t < Kc*32; t += 128) {
        int k = t >> 5, c = t & 31;
        sfs[k*33 + c] = fs[((size_t)n*Kc + k)*32 + c];
    }
    __syncthreads();

    // q·Kn per head per neighbor (warp h handles head h's 32-dim slice)
    float qh = sq[h*32 + lane];
    #pragma unroll 3
    for (int k = 0; k < Kc; k++) {
        float p = Kn[(size_t)sidx[k]*128 + h*32 + lane] * qh;
        p = wred(p);
        if (lane == 0) sqk[h][k] = p;
    }

    // per-head scalars + Qe2
    const float* sv_l  = g_sv  + l*128;
    const float* bv_l  = g_bv  + l*128;
    float sqv = wred(qh * sv_l[h*32 + lane]);
    float bqv = wred(qh * bv_l[h*32 + lane]);
    const float* Ath = g_At + l*4096 + h*1024;
    float qe2 = 0.f;
    #pragma unroll
    for (int j = 0; j < 32; j++) {
        float qj = __shfl_sync(0xffffffffu, qh, j);
        qe2 += Ath[j*32 + lane] * qj;
    }
    sQe2[h][lane] = qe2;
    __syncthreads();

    float mi = mask[n];
    float a = 0.f;
    {
        float x = -3.4028235e38f, mk = 0.f;
        if (lane < Kc) {
            mk = mi * smk[lane];
            float acc = bqv - sms_[lane] * sqv + sqk[h][lane];
            #pragma unroll
            for (int i = 0; i < 32; i++)
                acc += sfs[lane*33 + i] * sQe2[h][i];
            acc *= 0.17677669529663687f;
            x = (mk > 0.f) ? acc : -3.4028235e38f;
        }
        float mx = x;
        #pragma unroll
        for (int o = 16; o > 0; o >>= 1) mx = fmaxf(mx, __shfl_xor_sync(0xffffffffu, mx, o));
        float ex = (lane < Kc) ? expf(x - mx) : 0.f;
        float sm = wred(ex);
        a = (lane < Kc) ? (ex / sm) * mk : 0.f;
        sa[h][lane] = a;
    }
    float sa_tot = wred(a);
    float ma_tot = wred((lane < Kc) ? a * sms_[lane] : 0.f);
    if (lane == 0) { ssa[h] = sa_tot; sma[h] = ma_tot; }
    __syncwarp();

    float fa = 0.f;
    #pragma unroll 6
    for (int k = 0; k < Kc; k++)
        fa += sa[h][k] * sfs[k*33 + lane];
    sfa[h][lane] = fa;
    __syncthreads();

    // weighted Vn gather (global; L2-resident)
    float vacc = 0.f;
    #pragma unroll 6
    for (int k = 0; k < Kc; k++)
        vacc += sa[h][k] * Vn[(size_t)sidx[k]*128 + tid];
    const float* Wcv_l = g_Wcv + l*4096;
    float ed = 0.f;
    #pragma unroll 8
    for (int i = 0; i < 32; i++)
        ed += sfa[h][i] * Wcv_l[i*128 + tid];
    float od = vacc + ed - sma[h] * g_sv2[l*128 + tid] + ssa[h] * g_bv2[l*128 + tid];

    // ---- Wo projection + residual + LN1 ----
    satt[tid] = od;
    __syncthreads();
    float y = res[(size_t)n*128 + tid];
    #pragma unroll 8
    for (int c = 0; c < 128; c++)
        y += satt[c] * Wo_l[(size_t)c*128 + tid];

    float s = y, s2 = y * y;
    #pragma unroll
    for (int o = 16; o > 0; o >>= 1) {
        s  += __shfl_xor_sync(0xffffffffu, s,  o);
        s2 += __shfl_xor_sync(0xffffffffu, s2, o);
    }
    if (lane == 0) { ws[h] = s; ws2[h] = s2; }
    __syncthreads();
    s  = ws[0] + ws[1] + ws[2] + ws[3];
    s2 = ws2[0] + ws2[1] + ws2[2] + ws2[3];
    float mu = s * (1.f/128.f);
    float var = s2 * (1.f/128.f) - mu * mu;
    out[(size_t)n*128 + tid] = gamma[tid] * (y - mu) * rsqrtf(var + 1e-6f) + beta[tid];
}

// ---------------- final projection ----------------
__global__ void out_kernel(const float* __restrict__ hV, const float* __restrict__ Wout,
                           const float* __restrict__ bout, float* __restrict__ out)
{
    int node = blockIdx.x * 4 + (threadIdx.x >> 5);
    int lane = threadIdx.x & 31;
    if (node >= BNc) return;
    float acc = 0.f;
    #pragma unroll
    for (int m = 0; m < 4; m++)
        acc += hV[(size_t)node * 128 + lane + m * 32] * Wout[lane + m * 32];
    #pragma unroll
    for (int o = 16; o > 0; o >>= 1) acc += __shfl_xor_sync(0xffffffffu, acc, o);
    if (lane == 0) out[node] = acc + bout[0];
}

// ---------------- host launch ----------------
static void* symaddr(const void* sym) { void* p = nullptr; cudaGetSymbolAddress(&p, sym); return p; }

extern "C" void kernel_launch(void* const* d_in, const int* in_sizes, int n_in,
                              void* d_out, int out_size)
{
    const float* X      = (const float*)d_in[0];
    const float* V      = (const float*)d_in[1];
    const float* mask   = (const float*)d_in[2];
    const float* W_v    = (const float*)d_in[3];
    const float* b_v    = (const float*)d_in[4];
    const float* W_e    = (const float*)d_in[5];
    const float* b_e    = (const float*)d_in[6];
    const float* W_edge = (const float*)d_in[7];
    const float* ln_e_g = (const float*)d_in[8];
    const float* ln_e_b = (const float*)d_in[9];
    const float* Wq     = (const float*)d_in[10];
    const float* Wk     = (const float*)d_in[11];
    const float* Wv_a   = (const float*)d_in[12];
    const float* Wo     = (const float*)d_in[13];
    const float* ln1_g  = (const float*)d_in[14];
    const float* ln1_b  = (const float*)d_in[15];
    const float* ln2_g  = (const float*)d_in[16];
    const float* ln2_b  = (const float*)d_in[17];
    const float* W_ff1  = (const float*)d_in[18];
    const float* b_ff1  = (const float*)d_in[19];
    const float* W_ff2  = (const float*)d_in[20];
    const float* b_ff2  = (const float*)d_in[21];
    const float* W_out  = (const float*)d_in[22];
    const float* b_out  = (const float*)d_in[23];
    float* out = (float*)d_out;

    int*   pEidx = (int*)  symaddr(g_Eidx);
    float* pDnb  = (float*)symaddr(g_Dnb);
    float* pFs   = (float*)symaddr(g_fs);
    float* pMs   = (float*)symaddr(g_ms);
    float* phVa  = (float*)symaddr(g_hVa);
    float* phVb  = (float*)symaddr(g_hVb);
    float* phVm  = (float*)symaddr(g_hVm);
    float* pQ    = (float*)symaddr(g_Q);
    float* pKn   = (float*)symaddr(g_Kn);
    float* pVn   = (float*)symaddr(g_Vn);
    float* pFF   = (float*)symaddr(g_ff);

    const int gN128 = (BNc + 127) / 128;  // 47
    const int gN64  = (BNc + 63) / 64;    // 94

    topk_kernel<<<BNc, 256>>>(X, mask, pEidx, pDnb);
    pre1_kernel<<<3, 256>>>(W_edge, W_e, ln_e_g, ln_e_b, b_e);
    pre2_kernel<<<Lc, 256>>>(Wk, Wv_a);
    edge_fs_kernel<<<ECNT/8, 256>>>(pEidx, pDnb, pFs, pMs);
    sgemm_t<64,64,4,4,1,0><<<dim3(2, gN64), 256>>>(V, W_v, b_v, phVa, BNc, 128, 1024);

    float* cur = phVa;
    float* nxt = phVb;
    for (int l = 0; l < Lc; l++) {
        const float* Wk_bot = Wk   + (size_t)l*256*128 + 128*128;
        const float* Wv_bot = Wv_a + (size_t)l*256*128 + 128*128;
        sgemm_qkv_kernel<<<dim3(3, gN128), 256>>>(cur, Wq + (size_t)l*128*128, Wk_bot, Wv_bot,
                                                  pQ, pKn, pVn, BNc);
        attn4_kernel<<<BNc, 128>>>(pQ, pKn, pVn, pFs, pMs, pEidx, mask, l,
                                   Wo + (size_t)l*128*128, cur,
                                   ln1_g + l*128, ln1_b + l*128, phVm);
        sgemm_t<64,128,4,8,1,1><<<dim3(4, gN64), 256>>>(phVm, W_ff1 + (size_t)l*128*512,
                                                        b_ff1 + l*512, pFF, BNc, 512, 128);
        sgemm_ln_kernel<<<dim3(1, gN64), 256>>>(pFF, W_ff2 + (size_t)l*512*128, b_ff2 + l*128,
                                                phVm, ln2_g + l*128, ln2_b + l*128, mask,
                                                nxt, BNc, 512);
        float* t = cur; cur = nxt; nxt = t;
    }
    out_kernel<<<(BNc + 3) / 4, 128>>>(cur, W_out, b_out, out);
}

// round 6
// speedup vs baseline: 3.8907x; 1.3719x over previous
#include <cuda_runtime.h>
#include <math.h>
#include <stdint.h>

// ---------------- problem constants ----------------
#define Bc 4
#define Nc 1500
#define Kc 30
#define Lc 4
#define BNc (Bc*Nc)          // 6000
#define ECNT (BNc*Kc)        // 180000
#define SEG 188              // 8*188 >= 1500

// ---------------- device scratch ----------------
__device__ int   g_Eidx[ECNT];
__device__ float g_Dnb[ECNT];
__device__ float g_fs[(size_t)ECNT*32];
__device__ float g_ms[ECNT];
__device__ float g_hVa[(size_t)BNc*128];
__device__ float g_hVb[(size_t)BNc*128];
__device__ float g_hVm[(size_t)BNc*128];
__device__ float g_Q[(size_t)BNc*128];
__device__ float g_Kn[(size_t)BNc*128];
__device__ float g_Vn[(size_t)BNc*128];
__device__ float g_ff[(size_t)BNc*512];
// precomputed constants
__device__ float g_Wcomb[32*128];
__device__ float g_G[32*32];
__device__ float g_m[32];
__device__ float g_s[128];
__device__ float g_bp[128];
__device__ float g_At[Lc*4*32*32];
__device__ float g_sv[Lc*128];
__device__ float g_bv[Lc*128];
__device__ float g_Wcv[Lc*32*128];
__device__ float g_sv2[Lc*128];
__device__ float g_bv2[Lc*128];

__device__ __forceinline__ float wred(float v) {
    #pragma unroll
    for (int o = 16; o > 0; o >>= 1) v += __shfl_xor_sync(0xffffffffu, v, o);
    return v;
}

__device__ __forceinline__ uint32_t f2tf(float x) {
    uint32_t r; asm("cvt.rna.tf32.f32 %0, %1;" : "=r"(r) : "f"(x)); return r;
}

__device__ __forceinline__ void mma8(float* c, const uint32_t* a, const uint32_t* b) {
    asm volatile("mma.sync.aligned.m16n8k8.row.col.f32.tf32.tf32.f32 "
        "{%0,%1,%2,%3}, {%4,%5,%6,%7}, {%8,%9}, {%0,%1,%2,%3};"
        : "+f"(c[0]), "+f"(c[1]), "+f"(c[2]), "+f"(c[3])
        : "r"(a[0]), "r"(a[1]), "r"(a[2]), "r"(a[3]), "r"(b[0]), "r"(b[1]));
}

// ---------------- tf32 GEMM mainloop: 64x128 tile, 256 threads (2x4 warps) ----------------
__device__ __forceinline__ void tf32_loop(const float* __restrict__ A, const float* __restrict__ Bm,
    int M, int Nn, int Kk, int rowbase, int colbase,
    uint32_t As[64][17], uint32_t Bs[16][132], float acc[2][4][4])
{
    int tid = threadIdx.x;
    int warp = tid >> 5, lane = tid & 31;
    int g = lane >> 2, t = lane & 3;
    int warpRow = warp >> 2, warpCol = warp & 3;
    int ar = tid >> 2;
    int ac = (tid & 3) * 4;
    bool aval = (rowbase + ar) < M;
    const float* Arow = A + (size_t)(rowbase + ar) * Kk + ac;

    for (int k0 = 0; k0 < Kk; k0 += 16) {
        float4 av = aval ? *(const float4*)(Arow + k0) : make_float4(0.f,0.f,0.f,0.f);
        As[ar][ac+0] = f2tf(av.x); As[ar][ac+1] = f2tf(av.y);
        As[ar][ac+2] = f2tf(av.z); As[ar][ac+3] = f2tf(av.w);
        #pragma unroll
        for (int v = 0; v < 2; v++) {
            int idx = tid + v * 256;
            int br = idx >> 5, bc = (idx & 31) * 4;
            float4 bv = *(const float4*)(Bm + (size_t)(k0 + br) * Nn + colbase + bc);
            Bs[br][bc+0] = f2tf(bv.x); Bs[br][bc+1] = f2tf(bv.y);
            Bs[br][bc+2] = f2tf(bv.z); Bs[br][bc+3] = f2tf(bv.w);
        }
        __syncthreads();
        #pragma unroll
        for (int kk = 0; kk < 2; kk++) {
            uint32_t a[2][4], b[4][2];
            #pragma unroll
            for (int mi = 0; mi < 2; mi++) {
                int rb = warpRow * 32 + mi * 16;
                a[mi][0] = As[rb + g    ][kk*8 + t];
                a[mi][1] = As[rb + g + 8][kk*8 + t];
                a[mi][2] = As[rb + g    ][kk*8 + t + 4];
                a[mi][3] = As[rb + g + 8][kk*8 + t + 4];
            }
            #pragma unroll
            for (int ni = 0; ni < 4; ni++) {
                int cb = warpCol * 32 + ni * 8 + g;
                b[ni][0] = Bs[kk*8 + t    ][cb];
                b[ni][1] = Bs[kk*8 + t + 4][cb];
            }
            #pragma unroll
            for (int mi = 0; mi < 2; mi++)
                #pragma unroll
                for (int ni = 0; ni < 4; ni++)
                    mma8(acc[mi][ni], a[mi], b[ni]);
        }
        __syncthreads();
    }
}

// ---------------- tf32 GEMM + bias/relu ----------------
template<int BIAS, int RELU>
__global__ void __launch_bounds__(256)
tf32_gemm(const float* __restrict__ A, const float* __restrict__ Bm,
          const float* __restrict__ bias, float* __restrict__ C,
          int M, int Nn, int Kk)
{
    __shared__ uint32_t As[64][17];
    __shared__ uint32_t Bs[16][132];
    float acc[2][4][4];
    #pragma unroll
    for (int mi = 0; mi < 2; mi++)
        #pragma unroll
        for (int ni = 0; ni < 4; ni++)
            #pragma unroll
            for (int q = 0; q < 4; q++) acc[mi][ni][q] = 0.f;

    int rowbase = blockIdx.y * 64, colbase = blockIdx.x * 128;
    tf32_loop(A, Bm, M, Nn, Kk, rowbase, colbase, As, Bs, acc);

    int warp = threadIdx.x >> 5, lane = threadIdx.x & 31;
    int g = lane >> 2, t = lane & 3;
    int warpRow = warp >> 2, warpCol = warp & 3;
    #pragma unroll
    for (int mi = 0; mi < 2; mi++) {
        #pragma unroll
        for (int ni = 0; ni < 4; ni++) {
            int col = colbase + warpCol * 32 + ni * 8 + 2 * t;
            float b0 = BIAS ? bias[col]   : 0.f;
            float b1 = BIAS ? bias[col+1] : 0.f;
            int r0 = rowbase + warpRow * 32 + mi * 16 + g;
            if (r0 < M) {
                float2 o; o.x = acc[mi][ni][0] + b0; o.y = acc[mi][ni][1] + b1;
                if (RELU) { o.x = fmaxf(o.x, 0.f); o.y = fmaxf(o.y, 0.f); }
                *(float2*)(C + (size_t)r0 * Nn + col) = o;
            }
            int r1 = r0 + 8;
            if (r1 < M) {
                float2 o; o.x = acc[mi][ni][2] + b0; o.y = acc[mi][ni][3] + b1;
                if (RELU) { o.x = fmaxf(o.x, 0.f); o.y = fmaxf(o.y, 0.f); }
                *(float2*)(C + (size_t)r1 * Nn + col) = o;
            }
        }
    }
}

// ---------------- tf32 qkv GEMM (3 weights / outputs by blockIdx.x) ----------------
__global__ void __launch_bounds__(256)
tf32_gemm_qkv(const float* __restrict__ A,
              const float* __restrict__ B0, const float* __restrict__ B1, const float* __restrict__ B2,
              float* __restrict__ C0, float* __restrict__ C1, float* __restrict__ C2, int M)
{
    __shared__ uint32_t As[64][17];
    __shared__ uint32_t Bs[16][132];
    const float* Bm = (blockIdx.x == 0) ? B0 : (blockIdx.x == 1) ? B1 : B2;
    float* C = (blockIdx.x == 0) ? C0 : (blockIdx.x == 1) ? C1 : C2;
    float acc[2][4][4];
    #pragma unroll
    for (int mi = 0; mi < 2; mi++)
        #pragma unroll
        for (int ni = 0; ni < 4; ni++)
            #pragma unroll
            for (int q = 0; q < 4; q++) acc[mi][ni][q] = 0.f;

    int rowbase = blockIdx.y * 64;
    tf32_loop(A, Bm, M, 128, 128, rowbase, 0, As, Bs, acc);

    int warp = threadIdx.x >> 5, lane = threadIdx.x & 31;
    int g = lane >> 2, t = lane & 3;
    int warpRow = warp >> 2, warpCol = warp & 3;
    #pragma unroll
    for (int mi = 0; mi < 2; mi++) {
        #pragma unroll
        for (int ni = 0; ni < 4; ni++) {
            int col = warpCol * 32 + ni * 8 + 2 * t;
            int r0 = rowbase + warpRow * 32 + mi * 16 + g;
            if (r0 < M) {
                float2 o; o.x = acc[mi][ni][0]; o.y = acc[mi][ni][1];
                *(float2*)(C + (size_t)r0 * 128 + col) = o;
            }
            int r1 = r0 + 8;
            if (r1 < M) {
                float2 o; o.x = acc[mi][ni][2]; o.y = acc[mi][ni][3];
                *(float2*)(C + (size_t)r1 * 128 + col) = o;
            }
        }
    }
}

// ---------------- tf32 GEMM + bias + residual + LN2 + mask (N=128) ----------------
__global__ void __launch_bounds__(256)
tf32_gemm_ln(const float* __restrict__ A, const float* __restrict__ Bm,
             const float* __restrict__ bias, const float* __restrict__ res,
             const float* __restrict__ gamma, const float* __restrict__ beta,
             const float* __restrict__ mask, float* __restrict__ C,
             int M, int Kk)
{
    __shared__ uint32_t As[64][17];
    __shared__ uint32_t Bs[16][132];
    __shared__ float Vs[64][132];
    float acc[2][4][4];
    #pragma unroll
    for (int mi = 0; mi < 2; mi++)
        #pragma unroll
        for (int ni = 0; ni < 4; ni++)
            #pragma unroll
            for (int q = 0; q < 4; q++) acc[mi][ni][q] = 0.f;

    int rowbase = blockIdx.y * 64;
    tf32_loop(A, Bm, M, 128, Kk, rowbase, 0, As, Bs, acc);

    int tid = threadIdx.x;
    int warp = tid >> 5, lane = tid & 31;
    int g = lane >> 2, t = lane & 3;
    int warpRow = warp >> 2, warpCol = warp & 3;

    // stage v = gemm + bias + residual into smem
    #pragma unroll
    for (int mi = 0; mi < 2; mi++) {
        #pragma unroll
        for (int ni = 0; ni < 4; ni++) {
            int col = warpCol * 32 + ni * 8 + 2 * t;
            float b0 = bias[col], b1 = bias[col+1];
            int rl0 = warpRow * 32 + mi * 16 + g;
            int gr0 = rowbase + rl0;
            float r00 = (gr0 < M) ? res[(size_t)gr0 * 128 + col]     : 0.f;
            float r01 = (gr0 < M) ? res[(size_t)gr0 * 128 + col + 1] : 0.f;
            Vs[rl0][col]   = acc[mi][ni][0] + b0 + r00;
            Vs[rl0][col+1] = acc[mi][ni][1] + b1 + r01;
            int rl1 = rl0 + 8;
            int gr1 = gr0 + 8;
            float r10 = (gr1 < M) ? res[(size_t)gr1 * 128 + col]     : 0.f;
            float r11 = (gr1 < M) ? res[(size_t)gr1 * 128 + col + 1] : 0.f;
            Vs[rl1][col]   = acc[mi][ni][2] + b0 + r10;
            Vs[rl1][col+1] = acc[mi][ni][3] + b1 + r11;
        }
    }
    __syncthreads();

    // LN over each row: warp w handles rows w*8..w*8+7
    for (int rr = 0; rr < 8; rr++) {
        int rl = warp * 8 + rr;
        int gr = rowbase + rl;
        float4 v = *(float4*)(&Vs[rl][lane * 4]);
        float s  = v.x + v.y + v.z + v.w;
        float s2 = v.x*v.x + v.y*v.y + v.z*v.z + v.w*v.w;
        s = wred(s); s2 = wred(s2);
        if (gr >= M) continue;
        float mu  = s * (1.f/128.f);
        float var = s2 * (1.f/128.f) - mu * mu;
        float inv = rsqrtf(var + 1e-6f);
        float mk = mask[gr];
        int c0 = lane * 4;
        float4 o;
        o.x = mk * (gamma[c0+0] * (v.x - mu) * inv + beta[c0+0]);
        o.y = mk * (gamma[c0+1] * (v.y - mu) * inv + beta[c0+1]);
        o.z = mk * (gamma[c0+2] * (v.z - mu) * inv + beta[c0+2]);
        o.w = mk * (gamma[c0+3] * (v.w - mu) * inv + beta[c0+3]);
        *(float4*)(C + (size_t)gr * 128 + c0) = o;
    }
}

// ---------------- top-K nearest neighbors (segmented rescan) ----------------
__global__ void __launch_bounds__(256)
topk_kernel(const float* __restrict__ X, const float* __restrict__ mask,
            int* __restrict__ Eidx, float* __restrict__ Dnb)
{
    __shared__ float sD[Nc];
    __shared__ float wmin[8];
    __shared__ int   widx[8];
    __shared__ float red8[8];
    __shared__ float s_rowmax;
    __shared__ int   s_win;
    int row = blockIdx.x;
    int b = row / Nc;
    int i = row - b * Nc;
    int tid = threadIdx.x;
    int warp = tid >> 5, lane = tid & 31;
    const float* Xb = X + (size_t)b * Nc * 3;
    const float* mb = mask + (size_t)b * Nc;
    float xi0 = Xb[i*3+0], xi1 = Xb[i*3+1], xi2 = Xb[i*3+2];
    float mi = mb[i];
    float lmax = 0.f;
    for (int j = tid; j < Nc; j += 256) {
        float dx = xi0 - Xb[j*3+0];
        float dy = xi1 - Xb[j*3+1];
        float dz = xi2 - Xb[j*3+2];
        float d = sqrtf(dx*dx + dy*dy + dz*dz + 1e-6f);
        float D = mi * mb[j] * d;
        sD[j] = D;
        lmax = fmaxf(lmax, D);
    }
    #pragma unroll
    for (int o = 16; o > 0; o >>= 1) lmax = fmaxf(lmax, __shfl_xor_sync(0xffffffffu, lmax, o));
    if (lane == 0) red8[warp] = lmax;
    __syncthreads();
    if (tid == 0) {
        float m = red8[0];
        #pragma unroll
        for (int w = 1; w < 8; w++) m = fmaxf(m, red8[w]);
        s_rowmax = m;
    }
    __syncthreads();
    float rowmax = s_rowmax;
    for (int j = tid; j < Nc; j += 256) {
        float m2 = mi * mb[j];
        sD[j] = sD[j] + (1.f - m2) * rowmax;
    }
    __syncthreads();

    int s0 = warp * SEG;
    int s1 = min(Nc, s0 + SEG);
    {
        float v = 3.4e38f; int vi = 0x7fffffff;
        for (int j = s0 + lane; j < s1; j += 32) {
            float x = sD[j];
            if (x < v) { v = x; vi = j; }
        }
        #pragma unroll
        for (int o = 16; o > 0; o >>= 1) {
            float ov = __shfl_xor_sync(0xffffffffu, v, o);
            int   oi = __shfl_xor_sync(0xffffffffu, vi, o);
            if (ov < v || (ov == v && oi < vi)) { v = ov; vi = oi; }
        }
        if (lane == 0) { wmin[warp] = v; widx[warp] = vi; }
    }
    __syncthreads();

    for (int sel = 0; sel < Kc; sel++) {
        if (warp == 0) {
            float v = (lane < 8) ? wmin[lane] : 3.4e38f;
            int  vi = (lane < 8) ? widx[lane] : 0x7fffffff;
            #pragma unroll
            for (int o = 4; o > 0; o >>= 1) {
                float ov = __shfl_xor_sync(0xffffffffu, v, o);
                int   oi = __shfl_xor_sync(0xffffffffu, vi, o);
                if (ov < v || (ov == v && oi < vi)) { v = ov; vi = oi; }
            }
            if (lane == 0) {
                Eidx[(size_t)row*Kc + sel] = vi;
                Dnb [(size_t)row*Kc + sel] = v;
                sD[vi] = 3.4e38f;
                s_win = vi / SEG;
            }
        }
        __syncthreads();
        if (warp == s_win) {
            float v = 3.4e38f; int vi = 0x7fffffff;
            for (int j = s0 + lane; j < s1; j += 32) {
                float x = sD[j];
                if (x < v) { v = x; vi = j; }
            }
            #pragma unroll
            for (int o = 16; o > 0; o >>= 1) {
                float ov = __shfl_xor_sync(0xffffffffu, v, o);
                int   oi = __shfl_xor_sync(0xffffffffu, vi, o);
                if (ov < v || (ov == v && oi < vi)) { v = ov; vi = oi; }
            }
            if (lane == 0) { wmin[warp] = v; widx[warp] = vi; }
        }
        __syncthreads();
    }
}

// ---------------- precompute 1 ----------------
__global__ void pre1_kernel(const float* __restrict__ W_edge, const float* __restrict__ W_e,
                            const float* __restrict__ lng, const float* __restrict__ lnb,
                            const float* __restrict__ b_e)
{
    int tid = threadIdx.x;
    if (blockIdx.x == 0) {
        if (tid < 128) {
            float s = 0.f, bp = 0.f;
            for (int c = 0; c < 128; c++) {
                float w = W_e[(size_t)c*128 + tid];
                s  += lng[c] * w;
                bp += lnb[c] * w;
            }
            g_s[tid] = s;
            g_bp[tid] = bp + b_e[tid];
        }
    } else if (blockIdx.x == 1) {
        if (tid < 32) {
            float acc = 0.f;
            for (int c = 0; c < 128; c++) acc += W_edge[tid*128 + c];
            g_m[tid] = acc * (1.f/128.f);
        }
        for (int t = tid; t < 1024; t += 256) {
            int i = t >> 5, j = t & 31;
            float acc = 0.f;
            for (int c = 0; c < 128; c++) acc += W_edge[i*128+c] * W_edge[j*128+c];
            g_G[t] = acc;
        }
    } else {
        for (int t = tid; t < 4096; t += 256) {
            int i = t >> 7, d = t & 127;
            float acc = 0.f;
            for (int c = 0; c < 128; c++)
                acc += W_edge[i*128+c] * lng[c] * W_e[(size_t)c*128 + d];
            g_Wcomb[t] = acc;
        }
    }
}

// ---------------- precompute 2 ----------------
__global__ void pre2_kernel(const float* __restrict__ Wk, const float* __restrict__ Wv)
{
    int l = blockIdx.x;
    int tid = threadIdx.x;
    const float* Wk_l = Wk + (size_t)l * 256 * 128;
    const float* Wv_l = Wv + (size_t)l * 256 * 128;
    for (int t = tid; t < 4096; t += 256) {
        int h = t >> 10, r = t & 1023, j = r >> 5, i = r & 31;
        float acc = 0.f;
        for (int c = 0; c < 128; c++)
            acc += g_Wcomb[i*128+c] * Wk_l[(size_t)c*128 + h*32 + j];
        g_At[l*4096 + h*1024 + j*32 + i] = acc;
    }
    for (int t = tid; t < 4096; t += 256) {
        int i = t >> 7, d = t & 127;
        float acc = 0.f;
        for (int c = 0; c < 128; c++)
            acc += g_Wcomb[i*128+c] * Wv_l[(size_t)c*128 + d];
        g_Wcv[l*4096 + t] = acc;
    }
    if (tid < 128) {
        float sv = 0.f, bv = 0.f, sv2 = 0.f, bv2 = 0.f;
        for (int c = 0; c < 128; c++) {
            float wk = Wk_l[(size_t)c*128 + tid];
            float wv = Wv_l[(size_t)c*128 + tid];
            sv  += g_s[c]  * wk;
            bv  += g_bp[c] * wk;
            sv2 += g_s[c]  * wv;
            bv2 += g_bp[c] * wv;
        }
        g_sv [l*128 + tid] = sv;
        g_bv [l*128 + tid] = bv;
        g_sv2[l*128 + tid] = sv2;
        g_bv2[l*128 + tid] = bv2;
    }
}

// ---------------- fused edge features -> (feat/sigma, mu/sigma) ----------------
__global__ void __launch_bounds__(256)
edge_fs_kernel(const int* __restrict__ Eidx, const float* __restrict__ Dnb,
               float* __restrict__ fs, float* __restrict__ ms)
{
    __shared__ float sG[1024];
    __shared__ float sm[32];
    int tid = threadIdx.x;
    for (int t = tid; t < 1024; t += 256) sG[t] = g_G[t];
    if (tid < 32) sm[tid] = g_m[tid];
    __syncthreads();

    int e = blockIdx.x * 8 + (tid >> 5);
    int c = tid & 31;
    float f;
    if (c < 16) {
        int mdx = c & 7;
        float freq = expf((float)(2*mdx) * (-9.210340371976184f / 16.f));
        int node = e / Kc;
        int i = node % Nc;
        float d_rel = (float)(Eidx[e] - i);
        float ang = d_rel * freq;
        f = (c < 8) ? cosf(ang) : sinf(ang);
    } else {
        int r = c - 16;
        float mu = 20.f * (float)r / 15.f;
        float tt = (Dnb[e] - mu) * (1.f / 1.25f);
        f = expf(-tt * tt);
    }
    float mu = wred(f * sm[c]);
    float gf = 0.f;
    #pragma unroll
    for (int j = 0; j < 32; j++) {
        float fj = __shfl_sync(0xffffffffu, f, j);
        gf += sG[j*32 + c] * fj;
    }
    float ss = wred(f * gf);
    float var = ss * (1.f/128.f) - mu * mu;
    float inv = rsqrtf(var + 1e-6f);
    fs[(size_t)e*32 + c] = f * inv;
    if (c == 0) ms[e] = mu * inv;
}

// ---------------- fused neighbor attention + Wo + residual + LN1 ----------------
__global__ void __launch_bounds__(128)
attn4_kernel(const float* __restrict__ Q, const float* __restrict__ Kn, const float* __restrict__ Vn,
             const float* __restrict__ fs, const float* __restrict__ ms,
             const int* __restrict__ Eidx, const float* __restrict__ mask,
             int l, const float* __restrict__ Wo_l, const float* __restrict__ res,
             const float* __restrict__ gamma, const float* __restrict__ beta,
             float* __restrict__ out)
{
    __shared__ float sq[128];
    __shared__ float sfs[Kc*33];
    __shared__ float sqk[4][32];
    __shared__ float sQe2[4][32];
    __shared__ float sa[4][32];
    __shared__ float sfa[4][32];
    __shared__ float sms_[Kc], smk[Kc];
    __shared__ int   sidx[Kc];
    __shared__ float sma[4], ssa[4];
    __shared__ float satt[128];
    __shared__ float ws[4], ws2[4];

    int n = blockIdx.x;
    int tid = threadIdx.x;
    int h = tid >> 5, lane = tid & 31;
    int b = n / Nc;

    if (tid < Kc) {
        int j = Eidx[(size_t)n*Kc + tid];
        sidx[tid] = b * Nc + j;
        smk[tid]  = mask[(size_t)b*Nc + j];
        sms_[tid] = ms[(size_t)n*Kc + tid];
    }
    sq[tid] = Q[(size_t)n*128 + tid];
    for (int t = tid; t < Kc*32; t += 128) {
        int k = t >> 5, c = t & 31;
        sfs[k*33 + c] = fs[((size_t)n*Kc + k)*32 + c];
    }
    __syncthreads();

    float qh = sq[h*32 + lane];
    #pragma unroll 3
    for (int k = 0; k < Kc; k++) {
        float p = Kn[(size_t)sidx[k]*128 + h*32 + lane] * qh;
        p = wred(p);
        if (lane == 0) sqk[h][k] = p;
    }

    const float* sv_l  = g_sv  + l*128;
    const float* bv_l  = g_bv  + l*128;
    float sqv = wred(qh * sv_l[h*32 + lane]);
    float bqv = wred(qh * bv_l[h*32 + lane]);
    const float* Ath = g_At + l*4096 + h*1024;
    float qe2 = 0.f;
    #pragma unroll
    for (int j = 0; j < 32; j++) {
        float qj = __shfl_sync(0xffffffffu, qh, j);
        qe2 += Ath[j*32 + lane] * qj;
    }
    sQe2[h][lane] = qe2;
    __syncthreads();

    float mi = mask[n];
    float a = 0.f;
    {
        float x = -3.4028235e38f, mk = 0.f;
        if (lane < Kc) {
            mk = mi * smk[lane];
            float acc = bqv - sms_[lane] * sqv + sqk[h][lane];
            #pragma unroll
            for (int i = 0; i < 32; i++)
                acc += sfs[lane*33 + i] * sQe2[h][i];
            acc *= 0.17677669529663687f;
            x = (mk > 0.f) ? acc : -3.4028235e38f;
        }
        float mx = x;
        #pragma unroll
        for (int o = 16; o > 0; o >>= 1) mx = fmaxf(mx, __shfl_xor_sync(0xffffffffu, mx, o));
        float ex = (lane < Kc) ? expf(x - mx) : 0.f;
        float sm = wred(ex);
        a = (lane < Kc) ? (ex / sm) * mk : 0.f;
        sa[h][lane] = a;
    }
    float sa_tot = wred(a);
    float ma_tot = wred((lane < Kc) ? a * sms_[lane] : 0.f);
    if (lane == 0) { ssa[h] = sa_tot; sma[h] = ma_tot; }
    __syncwarp();

    float fa = 0.f;
    #pragma unroll 6
    for (int k = 0; k < Kc; k++)
        fa += sa[h][k] * sfs[k*33 + lane];
    sfa[h][lane] = fa;
    __syncthreads();

    float vacc = 0.f;
    #pragma unroll 6
    for (int k = 0; k < Kc; k++)
        vacc += sa[h][k] * Vn[(size_t)sidx[k]*128 + tid];
    const float* Wcv_l = g_Wcv + l*4096;
    float ed = 0.f;
    #pragma unroll 8
    for (int i = 0; i < 32; i++)
        ed += sfa[h][i] * Wcv_l[i*128 + tid];
    float od = vacc + ed - sma[h] * g_sv2[l*128 + tid] + ssa[h] * g_bv2[l*128 + tid];

    satt[tid] = od;
    __syncthreads();
    float y = res[(size_t)n*128 + tid];
    #pragma unroll 8
    for (int c = 0; c < 128; c++)
        y += satt[c] * Wo_l[(size_t)c*128 + tid];

    float s = y, s2 = y * y;
    #pragma unroll
    for (int o = 16; o > 0; o >>= 1) {
        s  += __shfl_xor_sync(0xffffffffu, s,  o);
        s2 += __shfl_xor_sync(0xffffffffu, s2, o);
    }
    if (lane == 0) { ws[h] = s; ws2[h] = s2; }
    __syncthreads();
    s  = ws[0] + ws[1] + ws[2] + ws[3];
    s2 = ws2[0] + ws2[1] + ws2[2] + ws2[3];
    float mu = s * (1.f/128.f);
    float var = s2 * (1.f/128.f) - mu * mu;
    out[(size_t)n*128 + tid] = gamma[tid] * (y - mu) * rsqrtf(var + 1e-6f) + beta[tid];
}

// ---------------- final projection ----------------
__global__ void out_kernel(const float* __restrict__ hV, const float* __restrict__ Wout,
                           const float* __restrict__ bout, float* __restrict__ out)
{
    int node = blockIdx.x * 4 + (threadIdx.x >> 5);
    int lane = threadIdx.x & 31;
    if (node >= BNc) return;
    float acc = 0.f;
    #pragma unroll
    for (int m = 0; m < 4; m++)
        acc += hV[(size_t)node * 128 + lane + m * 32] * Wout[lane + m * 32];
    #pragma unroll
    for (int o = 16; o > 0; o >>= 1) acc += __shfl_xor_sync(0xffffffffu, acc, o);
    if (lane == 0) out[node] = acc + bout[0];
}

// ---------------- host launch ----------------
static void* symaddr(const void* sym) { void* p = nullptr; cudaGetSymbolAddress(&p, sym); return p; }

extern "C" void kernel_launch(void* const* d_in, const int* in_sizes, int n_in,
                              void* d_out, int out_size)
{
    const float* X      = (const float*)d_in[0];
    const float* V      = (const float*)d_in[1];
    const float* mask   = (const float*)d_in[2];
    const float* W_v    = (const float*)d_in[3];
    const float* b_v    = (const float*)d_in[4];
    const float* W_e    = (const float*)d_in[5];
    const float* b_e    = (const float*)d_in[6];
    const float* W_edge = (const float*)d_in[7];
    const float* ln_e_g = (const float*)d_in[8];
    const float* ln_e_b = (const float*)d_in[9];
    const float* Wq     = (const float*)d_in[10];
    const float* Wk     = (const float*)d_in[11];
    const float* Wv_a   = (const float*)d_in[12];
    const float* Wo     = (const float*)d_in[13];
    const float* ln1_g  = (const float*)d_in[14];
    const float* ln1_b  = (const float*)d_in[15];
    const float* ln2_g  = (const float*)d_in[16];
    const float* ln2_b  = (const float*)d_in[17];
    const float* W_ff1  = (const float*)d_in[18];
    const float* b_ff1  = (const float*)d_in[19];
    const float* W_ff2  = (const float*)d_in[20];
    const float* b_ff2  = (const float*)d_in[21];
    const float* W_out  = (const float*)d_in[22];
    const float* b_out  = (const float*)d_in[23];
    float* out = (float*)d_out;

    int*   pEidx = (int*)  symaddr(g_Eidx);
    float* pDnb  = (float*)symaddr(g_Dnb);
    float* pFs   = (float*)symaddr(g_fs);
    float* pMs   = (float*)symaddr(g_ms);
    float* phVa  = (float*)symaddr(g_hVa);
    float* phVb  = (float*)symaddr(g_hVb);
    float* phVm  = (float*)symaddr(g_hVm);
    float* pQ    = (float*)symaddr(g_Q);
    float* pKn   = (float*)symaddr(g_Kn);
    float* pVn   = (float*)symaddr(g_Vn);
    float* pFF   = (float*)symaddr(g_ff);

    const int gN64 = (BNc + 63) / 64;    // 94

    topk_kernel<<<BNc, 256>>>(X, mask, pEidx, pDnb);
    pre1_kernel<<<3, 256>>>(W_edge, W_e, ln_e_g, ln_e_b, b_e);
    pre2_kernel<<<Lc, 256>>>(Wk, Wv_a);
    edge_fs_kernel<<<ECNT/8, 256>>>(pEidx, pDnb, pFs, pMs);
    tf32_gemm<1,0><<<dim3(1, gN64), 256>>>(V, W_v, b_v, phVa, BNc, 128, 1024);

    float* cur = phVa;
    float* nxt = phVb;
    for (int l = 0; l < Lc; l++) {
        const float* Wk_bot = Wk   + (size_t)l*256*128 + 128*128;
        const float* Wv_bot = Wv_a + (size_t)l*256*128 + 128*128;
        tf32_gemm_qkv<<<dim3(3, gN64), 256>>>(cur, Wq + (size_t)l*128*128, Wk_bot, Wv_bot,
                                              pQ, pKn, pVn, BNc);
        attn4_kernel<<<BNc, 128>>>(pQ, pKn, pVn, pFs, pMs, pEidx, mask, l,
                                   Wo + (size_t)l*128*128, cur,
                                   ln1_g + l*128, ln1_b + l*128, phVm);
        tf32_gemm<1,1><<<dim3(4, gN64), 256>>>(phVm, W_ff1 + (size_t)l*128*512,
                                               b_ff1 + l*512, pFF, BNc, 512, 128);
        tf32_gemm_ln<<<dim3(1, gN64), 256>>>(pFF, W_ff2 + (size_t)l*512*128, b_ff2 + l*128,
                                             phVm, ln2_g + l*128, ln2_b + l*128, mask,
                                             nxt, BNc, 512);
        float* t = cur; cur = nxt; nxt = t;
    }
    out_kernel<<<(BNc + 3) / 4, 128>>>(cur, W_out, b_out, out);
}